// round 3
// baseline (speedup 1.0000x reference)
#include <cuda_runtime.h>
#include <math.h>

// Problem shape (fixed by dataset)
#define L   4096
#define D   1024
#define SN  16
#define NC  64      // number of chunks
#define CT  64      // chunk length; NC*CT == L

// GEMM tiling
#define BM 128
#define BN 128
#define BK 16

// ---------------- scratch (static device globals; no allocation) ----------------
__device__ float g_xn[L * D];          // normalized input
__device__ float g_delta[L * D];       // selective delta
__device__ float g_sdx[L * D];         // sqrt(delta) * xn
__device__ float g_bpc[L * 2 * SN];    // per-t: Bp[0..15], C[16..31]
__device__ float g_cA[D * SN];         // 0.5 * A = -0.5*exp(A_log)
__device__ float g_P[NC * D * SN];     // per-chunk product of A_bar
__device__ float g_S[NC * D * SN];     // per-chunk end-state from h0=0
__device__ float g_hin[NC * D * SN];   // per-chunk initial state

// ---------------- helpers ----------------
__device__ __forceinline__ unsigned long long pack2(float lo, float hi) {
    unsigned long long r;
    asm("mov.b64 %0, {%1,%2};" : "=l"(r) : "f"(lo), "f"(hi));
    return r;
}
__device__ __forceinline__ void fma2(unsigned long long& d,
                                     unsigned long long a, unsigned long long b) {
    asm("fma.rn.f32x2 %0, %1, %2, %0;" : "+l"(d) : "l"(a), "l"(b));
}
__device__ __forceinline__ float2 unpack2(unsigned long long v) {
    float lo, hi;
    asm("mov.b64 {%0,%1}, %2;" : "=f"(lo), "=f"(hi) : "l"(v));
    return make_float2(lo, hi);
}
// denom > 1 always (A<0, delta>0), so approx reciprocal is safe & the eps-max is a no-op
__device__ __forceinline__ float frcp(float x) {
    float r;
    asm("rcp.approx.f32 %0, %1;" : "=f"(r) : "f"(x));
    return r;
}

// ---------------- kernel 0: cA = -0.5*exp(A_log) ----------------
__global__ void k_prep(const float* __restrict__ A_log) {
    int i = blockIdx.x * blockDim.x + threadIdx.x;
    if (i < D * SN) g_cA[i] = -0.5f * expf(A_log[i]);
}

// ---------------- kernel 1: RMSNorm ----------------
__global__ __launch_bounds__(256) void k_rms(const float* __restrict__ x,
                                             const float* __restrict__ w) {
    int row = blockIdx.x;
    int tid = threadIdx.x;
    const float4 xv = *(const float4*)(x + row * D + tid * 4);
    float s = xv.x * xv.x + xv.y * xv.y + xv.z * xv.z + xv.w * xv.w;
    #pragma unroll
    for (int o = 16; o > 0; o >>= 1) s += __shfl_xor_sync(0xFFFFFFFFu, s, o);
    __shared__ float red[8];
    int warp = tid >> 5, lane = tid & 31;
    if (lane == 0) red[warp] = s;
    __syncthreads();
    float tot = 0.f;
    #pragma unroll
    for (int i = 0; i < 8; i++) tot += red[i];
    float inv = 1.0f / sqrtf(tot * (1.0f / (float)D) + 1e-6f);
    const float4 wv = *(const float4*)(w + tid * 4);
    float4 o;
    o.x = wv.x * xv.x * inv;
    o.y = wv.y * xv.y * inv;
    o.z = wv.z * xv.z * inv;
    o.w = wv.w * xv.w * inv;
    *(float4*)(&g_xn[row * D + tid * 4]) = o;
}

// ---------------- kernel 2: Bp = xn@W_B, C = xn@W_C (small GEMM) ----------------
__global__ __launch_bounds__(128) void k_bc(const float* __restrict__ W_B,
                                            const float* __restrict__ W_C) {
    int t = blockIdx.x;
    int tid = threadIdx.x;
    __shared__ float sx[D];
    #pragma unroll
    for (int i = 0; i < D / 128; i++) sx[tid + i * 128] = g_xn[t * D + tid + i * 128];
    __syncthreads();
    int warp = tid >> 5, lane = tid & 31;
    for (int c = warp; c < 2 * SN; c += 4) {
        const float* W = (c < SN) ? W_B : W_C;
        int col = c & (SN - 1);
        float acc = 0.f;
        #pragma unroll 8
        for (int k = lane; k < D; k += 32)
            acc = fmaf(sx[k], W[k * SN + col], acc);
        #pragma unroll
        for (int o = 16; o > 0; o >>= 1) acc += __shfl_down_sync(0xFFFFFFFFu, acc, o);
        if (lane == 0) g_bpc[t * 2 * SN + c] = acc;
    }
}

// ---------------- kernel 3: Z = xn @ W_delta + b_delta, fused epilogue ----------------
// Produces g_delta = softclamp(softplus(Z)) and g_sdx = sqrt(delta)*xn.
__global__ __launch_bounds__(256) void k_gemm(const float* __restrict__ Wd,
                                              const float* __restrict__ bd) {
    __shared__ float As[BK][BM + 4];
    __shared__ float Bs[BK][BN + 4];
    int tid = threadIdx.x;
    int bm = blockIdx.y;                 // 32 tiles over L
    int bn = blockIdx.x;                 // 8 tiles over D
    const float* Aptr = g_xn + bm * BM * D;
    const float* Bptr = Wd + bn * BN;
    int tx = tid & 15, ty = tid >> 4;

    unsigned long long acc[8][4];
    #pragma unroll
    for (int i = 0; i < 8; i++)
        #pragma unroll
        for (int j = 0; j < 4; j++) acc[i][j] = 0ull;

    for (int k0 = 0; k0 < D; k0 += BK) {
        // A tile: 128 rows x 16 cols -> As[k][m]
        #pragma unroll
        for (int r = 0; r < 2; r++) {
            int idx = tid + r * 256;
            int row = idx >> 2;
            int c4 = idx & 3;
            float4 v = *(const float4*)(Aptr + row * D + k0 + c4 * 4);
            As[c4 * 4 + 0][row] = v.x;
            As[c4 * 4 + 1][row] = v.y;
            As[c4 * 4 + 2][row] = v.z;
            As[c4 * 4 + 3][row] = v.w;
        }
        // B tile: 16 rows x 128 cols -> Bs[k][n]
        #pragma unroll
        for (int r = 0; r < 2; r++) {
            int idx = tid + r * 256;
            int row = idx >> 5;
            int c4 = idx & 31;
            float4 v = *(const float4*)(Bptr + (size_t)(k0 + row) * D + c4 * 4);
            *(float4*)(&Bs[row][c4 * 4]) = v;
        }
        __syncthreads();
        #pragma unroll
        for (int kk = 0; kk < BK; kk++) {
            float4 a0 = *(const float4*)(&As[kk][ty * 8]);
            float4 a1 = *(const float4*)(&As[kk][ty * 8 + 4]);
            float4 b0 = *(const float4*)(&Bs[kk][tx * 8]);
            float4 b1 = *(const float4*)(&Bs[kk][tx * 8 + 4]);
            unsigned long long bb[4];
            bb[0] = pack2(b0.x, b0.y);
            bb[1] = pack2(b0.z, b0.w);
            bb[2] = pack2(b1.x, b1.y);
            bb[3] = pack2(b1.z, b1.w);
            float aa[8] = {a0.x, a0.y, a0.z, a0.w, a1.x, a1.y, a1.z, a1.w};
            #pragma unroll
            for (int i = 0; i < 8; i++) {
                unsigned long long av = pack2(aa[i], aa[i]);
                #pragma unroll
                for (int j = 0; j < 4; j++) fma2(acc[i][j], av, bb[j]);
            }
        }
        __syncthreads();
    }

    // epilogue: z -> delta -> (delta, sqrt(delta)*xn)
    const float CTR = 5.00005f, HLF = 4.99995f, INVH = 1.0f / 4.99995f;
    int gm = bm * BM + ty * 8;
    int gn = bn * BN + tx * 8;
    float4 bdl0 = *(const float4*)(bd + gn);
    float4 bdl1 = *(const float4*)(bd + gn + 4);
    float bdv[8] = {bdl0.x, bdl0.y, bdl0.z, bdl0.w, bdl1.x, bdl1.y, bdl1.z, bdl1.w};
    #pragma unroll
    for (int i = 0; i < 8; i++) {
        int m = gm + i;
        float z[8];
        #pragma unroll
        for (int j = 0; j < 4; j++) {
            float2 p = unpack2(acc[i][j]);
            z[2 * j] = p.x;
            z[2 * j + 1] = p.y;
        }
        float4 xv0 = *(const float4*)(&g_xn[(size_t)m * D + gn]);
        float4 xv1 = *(const float4*)(&g_xn[(size_t)m * D + gn + 4]);
        float xnv[8] = {xv0.x, xv0.y, xv0.z, xv0.w, xv1.x, xv1.y, xv1.z, xv1.w};
        float dl[8], sx[8];
        #pragma unroll
        for (int j = 0; j < 8; j++) {
            float zz = z[j] + bdv[j];
            float sp = fmaxf(zz, 0.0f) + log1pf(expf(-fabsf(zz)));
            float dlt = CTR + HLF * tanhf((sp - CTR) * INVH);
            dl[j] = dlt;
            sx[j] = sqrtf(dlt) * xnv[j];
        }
        *(float4*)(&g_delta[(size_t)m * D + gn])     = make_float4(dl[0], dl[1], dl[2], dl[3]);
        *(float4*)(&g_delta[(size_t)m * D + gn + 4]) = make_float4(dl[4], dl[5], dl[6], dl[7]);
        *(float4*)(&g_sdx[(size_t)m * D + gn])       = make_float4(sx[0], sx[1], sx[2], sx[3]);
        *(float4*)(&g_sdx[(size_t)m * D + gn + 4])   = make_float4(sx[4], sx[5], sx[6], sx[7]);
    }
}

// ---------------- kernel 4: chunk-local scan (products + end state) ----------------
__global__ __launch_bounds__(128) void k_phase2() {
    int gid = blockIdx.x * 128 + threadIdx.x;   // NC*D threads
    int c = gid >> 10;
    int d = gid & (D - 1);
    float cA[SN], h[SN], P[SN];
    #pragma unroll
    for (int q = 0; q < 4; q++) {
        float4 v = *(const float4*)(&g_cA[d * SN + q * 4]);
        cA[q * 4 + 0] = v.x; cA[q * 4 + 1] = v.y; cA[q * 4 + 2] = v.z; cA[q * 4 + 3] = v.w;
    }
    #pragma unroll
    for (int n = 0; n < SN; n++) { h[n] = 0.f; P[n] = 1.f; }

    int t0 = c * CT;
    for (int tt = 0; tt < CT; tt++) {
        int t = t0 + tt;
        float dlv = g_delta[(size_t)t * D + d];
        float sdx = g_sdx[(size_t)t * D + d];
        const float4* bp4 = (const float4*)(&g_bpc[t * 2 * SN]);
        float4 b0 = bp4[0], b1 = bp4[1], b2 = bp4[2], b3 = bp4[3];
        float bp[SN] = {b0.x, b0.y, b0.z, b0.w, b1.x, b1.y, b1.z, b1.w,
                        b2.x, b2.y, b2.z, b2.w, b3.x, b3.y, b3.z, b3.w};
        #pragma unroll
        for (int n = 0; n < SN; n++) {
            float hf = cA[n] * dlv;          // 0.5*delta*A  (always < 0)
            float den = 1.0f - hf;           // > 1, so eps-max is a no-op
            float dinv = frcp(den);
            float ab = (1.0f + hf) * dinv;
            float bx = sdx * bp[n] * dinv;
            h[n] = fmaf(ab, h[n], bx);
            P[n] *= ab;
        }
    }
    size_t base = (size_t)c * (D * SN) + (size_t)d * SN;
    #pragma unroll
    for (int q = 0; q < 4; q++) {
        *(float4*)(&g_P[base + q * 4]) = make_float4(P[q*4], P[q*4+1], P[q*4+2], P[q*4+3]);
        *(float4*)(&g_S[base + q * 4]) = make_float4(h[q*4], h[q*4+1], h[q*4+2], h[q*4+3]);
    }
}

// ---------------- kernel 5: scan over chunk summaries ----------------
__global__ __launch_bounds__(256) void k_phase3() {
    int s = blockIdx.x * 256 + threadIdx.x;  // D*SN threads
    float H = 0.f;
    #pragma unroll 4
    for (int c = 0; c < NC; c++) {
        size_t idx = (size_t)c * (D * SN) + s;
        g_hin[idx] = H;
        H = fmaf(g_P[idx], H, g_S[idx]);
    }
}

// ---------------- kernel 6: recompute recurrence with true init, emit y ----------------
__global__ __launch_bounds__(128) void k_phase4(const float* __restrict__ Dskip,
                                                float* __restrict__ y) {
    int gid = blockIdx.x * 128 + threadIdx.x;
    int c = gid >> 10;
    int d = gid & (D - 1);
    float cA[SN], h[SN];
    #pragma unroll
    for (int q = 0; q < 4; q++) {
        float4 v = *(const float4*)(&g_cA[d * SN + q * 4]);
        cA[q*4+0] = v.x; cA[q*4+1] = v.y; cA[q*4+2] = v.z; cA[q*4+3] = v.w;
    }
    size_t base = (size_t)c * (D * SN) + (size_t)d * SN;
    #pragma unroll
    for (int q = 0; q < 4; q++) {
        float4 v = *(const float4*)(&g_hin[base + q * 4]);
        h[q*4+0] = v.x; h[q*4+1] = v.y; h[q*4+2] = v.z; h[q*4+3] = v.w;
    }
    float dsk = Dskip[d];

    int t0 = c * CT;
    for (int tt = 0; tt < CT; tt++) {
        int t = t0 + tt;
        float dlv = g_delta[(size_t)t * D + d];
        float sdx = g_sdx[(size_t)t * D + d];
        float xnv = g_xn[(size_t)t * D + d];
        const float4* bc4 = (const float4*)(&g_bpc[t * 2 * SN]);
        float4 b0 = bc4[0], b1 = bc4[1], b2 = bc4[2], b3 = bc4[3];
        float4 c0 = bc4[4], c1 = bc4[5], c2 = bc4[6], c3 = bc4[7];
        float bp[SN] = {b0.x, b0.y, b0.z, b0.w, b1.x, b1.y, b1.z, b1.w,
                        b2.x, b2.y, b2.z, b2.w, b3.x, b3.y, b3.z, b3.w};
        float cc[SN] = {c0.x, c0.y, c0.z, c0.w, c1.x, c1.y, c1.z, c1.w,
                        c2.x, c2.y, c2.z, c2.w, c3.x, c3.y, c3.z, c3.w};
        float acc = 0.f;
        #pragma unroll
        for (int n = 0; n < SN; n++) {
            float hf = cA[n] * dlv;
            float den = 1.0f - hf;
            float dinv = frcp(den);
            float ab = (1.0f + hf) * dinv;
            float bx = sdx * bp[n] * dinv;
            h[n] = fmaf(ab, h[n], bx);
            acc = fmaf(cc[n], h[n], acc);
        }
        y[(size_t)t * D + d] = fmaf(dsk, xnv, acc);
    }
}

// ---------------- launch ----------------
extern "C" void kernel_launch(void* const* d_in, const int* in_sizes, int n_in,
                              void* d_out, int out_size) {
    const float* x       = (const float*)d_in[0];
    const float* A_log   = (const float*)d_in[1];
    const float* W_delta = (const float*)d_in[2];
    const float* b_delta = (const float*)d_in[3];
    const float* W_B     = (const float*)d_in[4];
    const float* W_C     = (const float*)d_in[5];
    const float* D_skip  = (const float*)d_in[6];
    const float* norm_w  = (const float*)d_in[7];
    float* y = (float*)d_out;

    k_prep<<<(D * SN + 255) / 256, 256>>>(A_log);
    k_rms<<<L, 256>>>(x, norm_w);
    k_bc<<<L, 128>>>(W_B, W_C);
    k_gemm<<<dim3(D / BN, L / BM), 256>>>(W_delta, b_delta);
    k_phase2<<<NC * D / 128, 128>>>();
    k_phase3<<<D * SN / 256, 256>>>();
    k_phase4<<<NC * D / 128, 128>>>(D_skip, y);
}

// round 5
// speedup vs baseline: 1.9544x; 1.9544x over previous
#include <cuda_runtime.h>
#include <cuda_bf16.h>
#include <math.h>
#include <stdint.h>

// Problem shape (fixed by dataset)
#define L   4096
#define D   1024
#define SN  16
#define NC  64      // number of chunks
#define CT  64      // chunk length; NC*CT == L

// ---------------- scratch (static device globals; no allocation) ----------------
__device__ float g_xn[L * D];                  // normalized input (fp32)
__device__ __nv_bfloat16 g_xh[L * D];          // bf16 hi of xn
__device__ __nv_bfloat16 g_xl[L * D];          // bf16 lo of xn
__device__ __nv_bfloat16 g_wth[D * D];         // W_delta^T hi  [n][k]
__device__ __nv_bfloat16 g_wtl[D * D];         // W_delta^T lo  [n][k]
__device__ float g_delta[L * D];               // selective delta
__device__ float g_sdx[L * D];                 // sqrt(delta) * xn
__device__ float g_bpc[L * 2 * SN];            // per-t: Bp[0..15], C[16..31]
__device__ float g_cA[D * SN];                 // 0.5 * A = -0.5*exp(A_log)
__device__ float g_P[NC * D * SN];             // per-chunk product of A_bar
__device__ float g_S[NC * D * SN];             // per-chunk end-state from h0=0
__device__ float g_hin[NC * D * SN];           // per-chunk initial state

// ---------------- helpers ----------------
__device__ __forceinline__ float frcp(float x) {
    float r;
    asm("rcp.approx.f32 %0, %1;" : "=f"(r) : "f"(x));
    return r;
}
__device__ __forceinline__ uint32_t smem_u32(const void* p) {
    uint32_t a;
    asm("{ .reg .u64 t; cvta.to.shared.u64 t, %1; cvt.u32.u64 %0, t; }" : "=r"(a) : "l"(p));
    return a;
}
__device__ __forceinline__ void ldsm4(uint32_t& r0, uint32_t& r1, uint32_t& r2, uint32_t& r3,
                                      uint32_t addr) {
    asm volatile("ldmatrix.sync.aligned.m8n8.x4.shared.b16 {%0,%1,%2,%3}, [%4];"
                 : "=r"(r0), "=r"(r1), "=r"(r2), "=r"(r3) : "r"(addr));
}
__device__ __forceinline__ void mma16816(float* d, const uint32_t* a, uint32_t b0, uint32_t b1) {
    asm volatile(
        "mma.sync.aligned.m16n8k16.row.col.f32.bf16.bf16.f32 "
        "{%0,%1,%2,%3}, {%4,%5,%6,%7}, {%8,%9}, {%0,%1,%2,%3};"
        : "+f"(d[0]), "+f"(d[1]), "+f"(d[2]), "+f"(d[3])
        : "r"(a[0]), "r"(a[1]), "r"(a[2]), "r"(a[3]), "r"(b0), "r"(b1));
}

// ---------------- kernel 0: cA = -0.5*exp(A_log) ----------------
__global__ void k_prep(const float* __restrict__ A_log) {
    int i = blockIdx.x * blockDim.x + threadIdx.x;
    if (i < D * SN) g_cA[i] = -0.5f * expf(A_log[i]);
}

// ---------------- kernel 0b: transpose + bf16-split W_delta ----------------
__global__ __launch_bounds__(256) void k_wt(const float* __restrict__ W) {
    __shared__ float tile[32][33];
    int bx = blockIdx.x, by = blockIdx.y;     // bx: n-tile, by: k-tile
    int tx = threadIdx.x, ty = threadIdx.y;   // 32 x 8
    #pragma unroll
    for (int i = 0; i < 32; i += 8)
        tile[ty + i][tx] = W[(size_t)(by * 32 + ty + i) * D + bx * 32 + tx];
    __syncthreads();
    #pragma unroll
    for (int i = 0; i < 32; i += 8) {
        int n = bx * 32 + ty + i;
        int k = by * 32 + tx;
        float v = tile[tx][ty + i];           // = W[k][n]
        __nv_bfloat16 h = __float2bfloat16(v);
        __nv_bfloat16 l = __float2bfloat16(v - __bfloat162float(h));
        g_wth[(size_t)n * D + k] = h;
        g_wtl[(size_t)n * D + k] = l;
    }
}

// ---------------- kernel 1: RMSNorm (+ bf16 split of xn) ----------------
__global__ __launch_bounds__(256) void k_rms(const float* __restrict__ x,
                                             const float* __restrict__ w) {
    int row = blockIdx.x;
    int tid = threadIdx.x;
    const float4 xv = *(const float4*)(x + (size_t)row * D + tid * 4);
    float s = xv.x * xv.x + xv.y * xv.y + xv.z * xv.z + xv.w * xv.w;
    #pragma unroll
    for (int o = 16; o > 0; o >>= 1) s += __shfl_xor_sync(0xFFFFFFFFu, s, o);
    __shared__ float red[8];
    int warp = tid >> 5, lane = tid & 31;
    if (lane == 0) red[warp] = s;
    __syncthreads();
    float tot = 0.f;
    #pragma unroll
    for (int i = 0; i < 8; i++) tot += red[i];
    float inv = 1.0f / sqrtf(tot * (1.0f / (float)D) + 1e-6f);
    const float4 wv = *(const float4*)(w + tid * 4);
    float4 o;
    o.x = wv.x * xv.x * inv;
    o.y = wv.y * xv.y * inv;
    o.z = wv.z * xv.z * inv;
    o.w = wv.w * xv.w * inv;
    size_t base = (size_t)row * D + tid * 4;
    *(float4*)(&g_xn[base]) = o;
    float vv[4] = {o.x, o.y, o.z, o.w};
    __nv_bfloat16 hh[4], ll[4];
    #pragma unroll
    for (int i = 0; i < 4; i++) {
        hh[i] = __float2bfloat16(vv[i]);
        ll[i] = __float2bfloat16(vv[i] - __bfloat162float(hh[i]));
    }
    ((__nv_bfloat162*)(&g_xh[base]))[0] = __halves2bfloat162(hh[0], hh[1]);
    ((__nv_bfloat162*)(&g_xh[base]))[1] = __halves2bfloat162(hh[2], hh[3]);
    ((__nv_bfloat162*)(&g_xl[base]))[0] = __halves2bfloat162(ll[0], ll[1]);
    ((__nv_bfloat162*)(&g_xl[base]))[1] = __halves2bfloat162(ll[2], ll[3]);
}

// ---------------- kernel 2: Bp = xn@W_B, C = xn@W_C (coalesced tiled GEMM) ----------------
#define BCR 64
__global__ __launch_bounds__(256) void k_bc2(const float* __restrict__ WB,
                                             const float* __restrict__ WC) {
    __shared__ float xs[BCR][68];
    __shared__ float ws[64][32];
    int tid = threadIdx.x;
    int t0 = blockIdx.x * BCR;
    int col = tid & 31, rg = tid >> 5;
    float acc[8];
    #pragma unroll
    for (int i = 0; i < 8; i++) acc[i] = 0.f;

    for (int k0 = 0; k0 < D; k0 += 64) {
        #pragma unroll
        for (int j = 0; j < 4; j++) {
            int id = tid + j * 256;            // 1024 float4 = 64x64 floats
            int r = id >> 4, c4 = id & 15;
            *(float4*)&xs[r][c4 * 4] =
                *(const float4*)(g_xn + (size_t)(t0 + r) * D + k0 + c4 * 4);
        }
        #pragma unroll
        for (int j = 0; j < 8; j++) {
            int id = tid + j * 256;            // 2048 = 64x32
            int kk = id >> 5, n = id & 31;
            ws[kk][n] = (n < SN) ? WB[(size_t)(k0 + kk) * SN + n]
                                 : WC[(size_t)(k0 + kk) * SN + n - SN];
        }
        __syncthreads();
        #pragma unroll 8
        for (int kk = 0; kk < 64; kk++) {
            float wv = ws[kk][col];
            #pragma unroll
            for (int i = 0; i < 8; i++) acc[i] = fmaf(xs[rg * 8 + i][kk], wv, acc[i]);
        }
        __syncthreads();
    }
    #pragma unroll
    for (int i = 0; i < 8; i++)
        g_bpc[(size_t)(t0 + rg * 8 + i) * 2 * SN + col] = acc[i];
}

// ---------------- kernel 3: Z = xn @ W_delta + b_delta via mma.sync bf16x3 ----------------
// CTA tile 128x128, 8 warps each 32(m) x 64(n). 3-term split: Ah*Bh + Ah*Bl + Al*Bh.
#define KST 40          // smem row stride in bf16 elements (80B; conflict-free ldmatrix)
__global__ __launch_bounds__(256, 2) void k_gemm_mma(const float* __restrict__ bd) {
    __shared__ __align__(16) __nv_bfloat16 sAh[128][KST];
    __shared__ __align__(16) __nv_bfloat16 sAl[128][KST];
    __shared__ __align__(16) __nv_bfloat16 sBh[128][KST];
    __shared__ __align__(16) __nv_bfloat16 sBl[128][KST];

    int tid = threadIdx.x, wid = tid >> 5, lane = tid & 31;
    int bm = blockIdx.y, bn = blockIdx.x;
    const int m0 = bm * 128, n0 = bn * 128;
    int wm = wid & 3, wn = wid >> 2;           // warp tile: rows wm*32, cols wn*64

    float acc[2][8][4];
    #pragma unroll
    for (int a = 0; a < 2; a++)
        #pragma unroll
        for (int b = 0; b < 8; b++)
            #pragma unroll
            for (int c = 0; c < 4; c++) acc[a][b][c] = 0.f;

    // ldmatrix source addresses (per-lane invariants)
    const uint32_t uAh = smem_u32(sAh), uAl = smem_u32(sAl);
    const uint32_t uBh = smem_u32(sBh), uBl = smem_u32(sBl);
    // A: row = wm*32 + atom*16 + (lane&15); k half-select = (lane>>4)*8 elems
    uint32_t aoff = (uint32_t)((wm * 32 + (lane & 15)) * (KST * 2) + ((lane >> 4) << 4));
    // B: row = wn*64 + nb*16 + (lane&7) + ((lane>>4)<<3); k half = ((lane>>3)&1)*8 elems
    uint32_t boff = (uint32_t)((wn * 64 + (lane & 7) + ((lane >> 4) << 3)) * (KST * 2) +
                               (((lane >> 3) & 1) << 4));

    // gmem->smem mapping: id -> row=id>>2, 16B seg=id&3
    int ldrow = tid >> 2, ldseg = tid & 3;

    for (int k0 = 0; k0 < D; k0 += 32) {
        #pragma unroll
        for (int j = 0; j < 2; j++) {
            int row = ldrow + j * 64;
            size_t ga = (size_t)(m0 + row) * D + k0 + ldseg * 8;
            size_t gb = (size_t)(n0 + row) * D + k0 + ldseg * 8;
            *(uint4*)(&sAh[row][ldseg * 8]) = *(const uint4*)(g_xh + ga);
            *(uint4*)(&sAl[row][ldseg * 8]) = *(const uint4*)(g_xl + ga);
            *(uint4*)(&sBh[row][ldseg * 8]) = *(const uint4*)(g_wth + gb);
            *(uint4*)(&sBl[row][ldseg * 8]) = *(const uint4*)(g_wtl + gb);
        }
        __syncthreads();
        #pragma unroll
        for (int kk = 0; kk < 2; kk++) {
            uint32_t kb = (uint32_t)(kk * 32);   // 16 bf16 = 32 bytes
            uint32_t ah0[4], ah1[4], al0[4], al1[4];
            ldsm4(ah0[0], ah0[1], ah0[2], ah0[3], uAh + aoff + kb);
            ldsm4(ah1[0], ah1[1], ah1[2], ah1[3], uAh + aoff + kb + 16 * KST * 2);
            ldsm4(al0[0], al0[1], al0[2], al0[3], uAl + aoff + kb);
            ldsm4(al1[0], al1[1], al1[2], al1[3], uAl + aoff + kb + 16 * KST * 2);
            #pragma unroll
            for (int nb = 0; nb < 4; nb++) {
                uint32_t bh[4], bl[4];
                uint32_t bo = boff + kb + (uint32_t)(nb * 16 * KST * 2);
                ldsm4(bh[0], bh[1], bh[2], bh[3], uBh + bo);
                ldsm4(bl[0], bl[1], bl[2], bl[3], uBl + bo);
                // n-atom 2*nb uses (bh[0],bh[1]); atom 2*nb+1 uses (bh[2],bh[3])
                mma16816(acc[0][2 * nb], ah0, bh[0], bh[1]);
                mma16816(acc[0][2 * nb], ah0, bl[0], bl[1]);
                mma16816(acc[0][2 * nb], al0, bh[0], bh[1]);
                mma16816(acc[1][2 * nb], ah1, bh[0], bh[1]);
                mma16816(acc[1][2 * nb], ah1, bl[0], bl[1]);
                mma16816(acc[1][2 * nb], al1, bh[0], bh[1]);
                mma16816(acc[0][2 * nb + 1], ah0, bh[2], bh[3]);
                mma16816(acc[0][2 * nb + 1], ah0, bl[2], bl[3]);
                mma16816(acc[0][2 * nb + 1], al0, bh[2], bh[3]);
                mma16816(acc[1][2 * nb + 1], ah1, bh[2], bh[3]);
                mma16816(acc[1][2 * nb + 1], ah1, bl[2], bl[3]);
                mma16816(acc[1][2 * nb + 1], al1, bh[2], bh[3]);
            }
        }
        __syncthreads();
    }

    // epilogue: z -> delta -> (delta, sqrt(delta)*xn), direct stores (float2)
    const float CTR = 5.00005f, HLF = 4.99995f, INVH = 1.0f / 4.99995f;
    #pragma unroll
    for (int ma = 0; ma < 2; ma++) {
        int row0 = m0 + wm * 32 + ma * 16 + (lane >> 2);
        #pragma unroll
        for (int na = 0; na < 8; na++) {
            int col = n0 + wn * 64 + na * 8 + 2 * (lane & 3);
            float2 bdv = *(const float2*)(bd + col);
            #pragma unroll
            for (int hrow = 0; hrow < 2; hrow++) {
                int m = row0 + hrow * 8;
                float z0 = acc[ma][na][2 * hrow]     + bdv.x;
                float z1 = acc[ma][na][2 * hrow + 1] + bdv.y;
                float2 xv = *(const float2*)(&g_xn[(size_t)m * D + col]);
                float sp0 = fmaxf(z0, 0.0f) + log1pf(expf(-fabsf(z0)));
                float sp1 = fmaxf(z1, 0.0f) + log1pf(expf(-fabsf(z1)));
                float dl0 = CTR + HLF * tanhf((sp0 - CTR) * INVH);
                float dl1 = CTR + HLF * tanhf((sp1 - CTR) * INVH);
                float sx0 = sqrtf(dl0) * xv.x;
                float sx1 = sqrtf(dl1) * xv.y;
                *(float2*)(&g_delta[(size_t)m * D + col]) = make_float2(dl0, dl1);
                *(float2*)(&g_sdx[(size_t)m * D + col])   = make_float2(sx0, sx1);
            }
        }
    }
}

// ---------------- kernel 4: chunk-local scan (products + end state) ----------------
__global__ __launch_bounds__(128) void k_phase2() {
    int gid = blockIdx.x * 128 + threadIdx.x;   // NC*D threads
    int c = gid >> 10;
    int d = gid & (D - 1);
    float cA[SN], h[SN], P[SN];
    #pragma unroll
    for (int q = 0; q < 4; q++) {
        float4 v = *(const float4*)(&g_cA[d * SN + q * 4]);
        cA[q * 4 + 0] = v.x; cA[q * 4 + 1] = v.y; cA[q * 4 + 2] = v.z; cA[q * 4 + 3] = v.w;
    }
    #pragma unroll
    for (int n = 0; n < SN; n++) { h[n] = 0.f; P[n] = 1.f; }

    int t0 = c * CT;
    for (int tt = 0; tt < CT; tt++) {
        int t = t0 + tt;
        float dlv = g_delta[(size_t)t * D + d];
        float sdx = g_sdx[(size_t)t * D + d];
        const float4* bp4 = (const float4*)(&g_bpc[t * 2 * SN]);
        float4 b0 = bp4[0], b1 = bp4[1], b2 = bp4[2], b3 = bp4[3];
        float bp[SN] = {b0.x, b0.y, b0.z, b0.w, b1.x, b1.y, b1.z, b1.w,
                        b2.x, b2.y, b2.z, b2.w, b3.x, b3.y, b3.z, b3.w};
        #pragma unroll
        for (int n = 0; n < SN; n++) {
            float hf = cA[n] * dlv;          // 0.5*delta*A  (always < 0)
            float den = 1.0f - hf;           // > 1, eps-max provably no-op
            float dinv = frcp(den);
            float ab = (1.0f + hf) * dinv;
            float bx = sdx * bp[n] * dinv;
            h[n] = fmaf(ab, h[n], bx);
            P[n] *= ab;
        }
    }
    size_t basei = (size_t)c * (D * SN) + (size_t)d * SN;
    #pragma unroll
    for (int q = 0; q < 4; q++) {
        *(float4*)(&g_P[basei + q * 4]) = make_float4(P[q*4], P[q*4+1], P[q*4+2], P[q*4+3]);
        *(float4*)(&g_S[basei + q * 4]) = make_float4(h[q*4], h[q*4+1], h[q*4+2], h[q*4+3]);
    }
}

// ---------------- kernel 5: scan over chunk summaries ----------------
__global__ __launch_bounds__(256) void k_phase3() {
    int s = blockIdx.x * 256 + threadIdx.x;  // D*SN threads
    float H = 0.f;
    #pragma unroll 4
    for (int c = 0; c < NC; c++) {
        size_t idx = (size_t)c * (D * SN) + s;
        g_hin[idx] = H;
        H = fmaf(g_P[idx], H, g_S[idx]);
    }
}

// ---------------- kernel 6: recompute recurrence with true init, emit y ----------------
__global__ __launch_bounds__(128) void k_phase4(const float* __restrict__ Dskip,
                                                float* __restrict__ y) {
    int gid = blockIdx.x * 128 + threadIdx.x;
    int c = gid >> 10;
    int d = gid & (D - 1);
    float cA[SN], h[SN];
    #pragma unroll
    for (int q = 0; q < 4; q++) {
        float4 v = *(const float4*)(&g_cA[d * SN + q * 4]);
        cA[q*4+0] = v.x; cA[q*4+1] = v.y; cA[q*4+2] = v.z; cA[q*4+3] = v.w;
    }
    size_t basei = (size_t)c * (D * SN) + (size_t)d * SN;
    #pragma unroll
    for (int q = 0; q < 4; q++) {
        float4 v = *(const float4*)(&g_hin[basei + q * 4]);
        h[q*4+0] = v.x; h[q*4+1] = v.y; h[q*4+2] = v.z; h[q*4+3] = v.w;
    }
    float dsk = Dskip[d];

    int t0 = c * CT;
    for (int tt = 0; tt < CT; tt++) {
        int t = t0 + tt;
        float dlv = g_delta[(size_t)t * D + d];
        float sdx = g_sdx[(size_t)t * D + d];
        float xnv = g_xn[(size_t)t * D + d];
        const float4* bc4 = (const float4*)(&g_bpc[t * 2 * SN]);
        float4 b0 = bc4[0], b1 = bc4[1], b2 = bc4[2], b3 = bc4[3];
        float4 c0 = bc4[4], c1 = bc4[5], c2 = bc4[6], c3 = bc4[7];
        float bp[SN] = {b0.x, b0.y, b0.z, b0.w, b1.x, b1.y, b1.z, b1.w,
                        b2.x, b2.y, b2.z, b2.w, b3.x, b3.y, b3.z, b3.w};
        float cc[SN] = {c0.x, c0.y, c0.z, c0.w, c1.x, c1.y, c1.z, c1.w,
                        c2.x, c2.y, c2.z, c2.w, c3.x, c3.y, c3.z, c3.w};
        float acc = 0.f;
        #pragma unroll
        for (int n = 0; n < SN; n++) {
            float hf = cA[n] * dlv;
            float den = 1.0f - hf;
            float dinv = frcp(den);
            float ab = (1.0f + hf) * dinv;
            float bx = sdx * bp[n] * dinv;
            h[n] = fmaf(ab, h[n], bx);
            acc = fmaf(cc[n], h[n], acc);
        }
        y[(size_t)t * D + d] = fmaf(dsk, xnv, acc);
    }
}

// ---------------- launch ----------------
extern "C" void kernel_launch(void* const* d_in, const int* in_sizes, int n_in,
                              void* d_out, int out_size) {
    const float* x       = (const float*)d_in[0];
    const float* A_log   = (const float*)d_in[1];
    const float* W_delta = (const float*)d_in[2];
    const float* b_delta = (const float*)d_in[3];
    const float* W_B     = (const float*)d_in[4];
    const float* W_C     = (const float*)d_in[5];
    const float* D_skip  = (const float*)d_in[6];
    const float* norm_w  = (const float*)d_in[7];
    float* y = (float*)d_out;

    k_prep<<<(D * SN + 255) / 256, 256>>>(A_log);
    k_wt<<<dim3(32, 32), dim3(32, 8)>>>(W_delta);
    k_rms<<<L, 256>>>(x, norm_w);
    k_bc2<<<L / BCR, 256>>>(W_B, W_C);
    k_gemm_mma<<<dim3(D / 128, L / 128), 256>>>(b_delta);
    k_phase2<<<NC * D / 128, 128>>>();
    k_phase3<<<D * SN / 256, 256>>>();
    k_phase4<<<NC * D / 128, 128>>>(D_skip, y);
}

// round 6
// speedup vs baseline: 2.5523x; 1.3059x over previous
#include <cuda_runtime.h>
#include <cuda_bf16.h>
#include <math.h>
#include <stdint.h>

// Problem shape (fixed by dataset)
#define L   4096
#define D   1024
#define SN  16
#define NC  64      // number of chunks
#define CT  64      // chunk length; NC*CT == L

typedef unsigned long long u64;

// ---------------- scratch (static device globals; no allocation) ----------------
__device__ float g_xn[L * D];                  // normalized input (fp32)
__device__ __nv_bfloat16 g_xh[L * D];          // bf16 hi of xn
__device__ __nv_bfloat16 g_xl[L * D];          // bf16 lo of xn
__device__ __nv_bfloat16 g_wth[D * D];         // W_delta^T hi  [n][k]
__device__ __nv_bfloat16 g_wtl[D * D];         // W_delta^T lo  [n][k]
__device__ __nv_bfloat16 g_wbch[128 * D];      // [WB|WC|0]^T hi [n][k], n<32 real
__device__ __nv_bfloat16 g_wbcl[128 * D];      // [WB|WC|0]^T lo
__device__ float g_delta[L * D];               // selective delta
__device__ float g_sdx[L * D];                 // sqrt(delta) * xn
__device__ float g_bpc[L * 2 * SN];            // per-t: Bp[0..15], C[16..31]
__device__ float g_cA[D * SN];                 // +0.5*exp(A_log)   (positive!)
__device__ float g_P[NC * D * SN];             // per-chunk product of A_bar
__device__ float g_S[NC * D * SN];             // per-chunk end-state from h0=0
__device__ float g_hin[NC * D * SN];           // per-chunk initial state

// ---------------- helpers ----------------
__device__ __forceinline__ float frcp(float x) {
    float r;
    asm("rcp.approx.f32 %0, %1;" : "=f"(r) : "f"(x));
    return r;
}
__device__ __forceinline__ uint32_t smem_u32(const void* p) {
    uint32_t a;
    asm("{ .reg .u64 t; cvta.to.shared.u64 t, %1; cvt.u32.u64 %0, t; }" : "=r"(a) : "l"(p));
    return a;
}
__device__ __forceinline__ void ldsm4(uint32_t& r0, uint32_t& r1, uint32_t& r2, uint32_t& r3,
                                      uint32_t addr) {
    asm volatile("ldmatrix.sync.aligned.m8n8.x4.shared.b16 {%0,%1,%2,%3}, [%4];"
                 : "=r"(r0), "=r"(r1), "=r"(r2), "=r"(r3) : "r"(addr));
}
__device__ __forceinline__ void mma16816(float* d, const uint32_t* a, uint32_t b0, uint32_t b1) {
    asm volatile(
        "mma.sync.aligned.m16n8k16.row.col.f32.bf16.bf16.f32 "
        "{%0,%1,%2,%3}, {%4,%5,%6,%7}, {%8,%9}, {%0,%1,%2,%3};"
        : "+f"(d[0]), "+f"(d[1]), "+f"(d[2]), "+f"(d[3])
        : "r"(a[0]), "r"(a[1]), "r"(a[2]), "r"(a[3]), "r"(b0), "r"(b1));
}
__device__ __forceinline__ void cp16(uint32_t dst, const void* src) {
    asm volatile("cp.async.cg.shared.global [%0], [%1], 16;" :: "r"(dst), "l"(src) : "memory");
}
__device__ __forceinline__ u64 pack2(float lo, float hi) {
    u64 r;
    asm("mov.b64 %0, {%1,%2};" : "=l"(r) : "f"(lo), "f"(hi));
    return r;
}
__device__ __forceinline__ float2 unpack2(u64 v) {
    float lo, hi;
    asm("mov.b64 {%0,%1}, %2;" : "=f"(lo), "=f"(hi) : "l"(v));
    return make_float2(lo, hi);
}
__device__ __forceinline__ u64 fma2(u64 a, u64 b, u64 c) {
    u64 d;
    asm("fma.rn.f32x2 %0, %1, %2, %3;" : "=l"(d) : "l"(a), "l"(b), "l"(c));
    return d;
}
__device__ __forceinline__ u64 mul2(u64 a, u64 b) {
    u64 d;
    asm("mul.rn.f32x2 %0, %1, %2;" : "=l"(d) : "l"(a), "l"(b));
    return d;
}
__device__ __forceinline__ u64 add2(u64 a, u64 b) {
    u64 d;
    asm("add.rn.f32x2 %0, %1, %2;" : "=l"(d) : "l"(a), "l"(b));
    return d;
}

// ---------------- kernel 0: cA = +0.5*exp(A_log) ----------------
__global__ void k_prep(const float* __restrict__ A_log) {
    int i = blockIdx.x * blockDim.x + threadIdx.x;
    if (i < D * SN) g_cA[i] = 0.5f * expf(A_log[i]);
}

// ---------------- kernel 0b: transpose + bf16-split W_delta ----------------
__global__ __launch_bounds__(256) void k_wt(const float* __restrict__ W) {
    __shared__ float tile[32][33];
    int bx = blockIdx.x, by = blockIdx.y;
    int tx = threadIdx.x, ty = threadIdx.y;   // 32 x 8
    #pragma unroll
    for (int i = 0; i < 32; i += 8)
        tile[ty + i][tx] = W[(size_t)(by * 32 + ty + i) * D + bx * 32 + tx];
    __syncthreads();
    #pragma unroll
    for (int i = 0; i < 32; i += 8) {
        int n = bx * 32 + ty + i;
        int k = by * 32 + tx;
        float v = tile[tx][ty + i];           // = W[k][n]
        __nv_bfloat16 h = __float2bfloat16(v);
        __nv_bfloat16 l = __float2bfloat16(v - __bfloat162float(h));
        g_wth[(size_t)n * D + k] = h;
        g_wtl[(size_t)n * D + k] = l;
    }
}

// ---------------- kernel 0c: pack [WB|WC|0]^T, bf16 split ----------------
__global__ __launch_bounds__(256) void k_wbc(const float* __restrict__ WB,
                                             const float* __restrict__ WC) {
    int idx = blockIdx.x * 256 + threadIdx.x;   // 128*1024
    int n = idx >> 10, k = idx & 1023;
    float v = 0.f;
    if (n < SN) v = WB[(size_t)k * SN + n];
    else if (n < 2 * SN) v = WC[(size_t)k * SN + n - SN];
    __nv_bfloat16 h = __float2bfloat16(v);
    __nv_bfloat16 l = __float2bfloat16(v - __bfloat162float(h));
    g_wbch[idx] = h;
    g_wbcl[idx] = l;
}

// ---------------- kernel 1: RMSNorm (+ bf16 split of xn) ----------------
__global__ __launch_bounds__(256) void k_rms(const float* __restrict__ x,
                                             const float* __restrict__ w) {
    int row = blockIdx.x;
    int tid = threadIdx.x;
    const float4 xv = *(const float4*)(x + (size_t)row * D + tid * 4);
    float s = xv.x * xv.x + xv.y * xv.y + xv.z * xv.z + xv.w * xv.w;
    #pragma unroll
    for (int o = 16; o > 0; o >>= 1) s += __shfl_xor_sync(0xFFFFFFFFu, s, o);
    __shared__ float red[8];
    int warp = tid >> 5, lane = tid & 31;
    if (lane == 0) red[warp] = s;
    __syncthreads();
    float tot = 0.f;
    #pragma unroll
    for (int i = 0; i < 8; i++) tot += red[i];
    float inv = 1.0f / sqrtf(tot * (1.0f / (float)D) + 1e-6f);
    const float4 wv = *(const float4*)(w + tid * 4);
    float4 o;
    o.x = wv.x * xv.x * inv;
    o.y = wv.y * xv.y * inv;
    o.z = wv.z * xv.z * inv;
    o.w = wv.w * xv.w * inv;
    size_t base = (size_t)row * D + tid * 4;
    *(float4*)(&g_xn[base]) = o;
    float vv[4] = {o.x, o.y, o.z, o.w};
    __nv_bfloat16 hh[4], ll[4];
    #pragma unroll
    for (int i = 0; i < 4; i++) {
        hh[i] = __float2bfloat16(vv[i]);
        ll[i] = __float2bfloat16(vv[i] - __bfloat162float(hh[i]));
    }
    ((__nv_bfloat162*)(&g_xh[base]))[0] = __halves2bfloat162(hh[0], hh[1]);
    ((__nv_bfloat162*)(&g_xh[base]))[1] = __halves2bfloat162(hh[2], hh[3]);
    ((__nv_bfloat162*)(&g_xl[base]))[0] = __halves2bfloat162(ll[0], ll[1]);
    ((__nv_bfloat162*)(&g_xl[base]))[1] = __halves2bfloat162(ll[2], ll[3]);
}

// ---------------- kernel 3: fused GEMM (delta + Bp/C) via mma.sync bf16x3 ----------------
// grid (9, 32): bn<8 -> Z=xn@W_delta tile; bn==8 -> [Bp|C]=xn@[WB|WC] tile.
// CTA tile 128x128, 8 warps each 32(m) x 64(n). cp.async 2-stage pipeline.
#define KST 40                       // smem row stride in bf16 (80B)
#define TILE_B (128 * KST * 2)       // 10240 B per tile
#define STAGE_B (4 * TILE_B)         // 40960 B per stage
__global__ __launch_bounds__(256, 2) void k_gemm_mma(const float* __restrict__ bd) {
    extern __shared__ __align__(16) char smem[];
    const uint32_t su = smem_u32(smem);

    int tid = threadIdx.x, wid = tid >> 5, lane = tid & 31;
    int bm = blockIdx.y, bn = blockIdx.x;
    const bool isbc = (bn == 8);
    const int m0 = bm * 128, n0 = bn * 128;
    int wm = wid & 3, wn = wid >> 2;

    const __nv_bfloat16* pA0 = g_xh + (size_t)m0 * D;
    const __nv_bfloat16* pA1 = g_xl + (size_t)m0 * D;
    const __nv_bfloat16* pB0 = isbc ? g_wbch : g_wth + (size_t)n0 * D;
    const __nv_bfloat16* pB1 = isbc ? g_wbcl : g_wtl + (size_t)n0 * D;

    float acc[2][8][4];
    #pragma unroll
    for (int a = 0; a < 2; a++)
        #pragma unroll
        for (int b = 0; b < 8; b++)
            #pragma unroll
            for (int c = 0; c < 4; c++) acc[a][b][c] = 0.f;

    // ldmatrix per-lane offsets (within a stage)
    uint32_t aoff = (uint32_t)((wm * 32 + (lane & 15)) * (KST * 2) + ((lane >> 4) << 4));
    uint32_t boff = (uint32_t)((wn * 64 + (lane & 7) + ((lane >> 4) << 3)) * (KST * 2) +
                               (((lane >> 3) & 1) << 4));

    // gmem->smem: 2048 16B segs per k-step; j>>1 = tile (compile time)
    auto issue = [&](int k0, int stage) {
        uint32_t sb = su + (uint32_t)(stage * STAGE_B);
        #pragma unroll
        for (int j = 0; j < 8; j++) {
            const int tile = j >> 1;
            int sub = tid + (j & 1) * 256;          // 0..511
            int row = sub >> 2, seg = sub & 3;
            const __nv_bfloat16* src;
            if (tile == 0)      src = pA0 + (size_t)row * D + k0 + seg * 8;
            else if (tile == 1) src = pA1 + (size_t)row * D + k0 + seg * 8;
            else if (tile == 2) src = pB0 + (size_t)row * D + k0 + seg * 8;
            else                src = pB1 + (size_t)row * D + k0 + seg * 8;
            cp16(sb + (uint32_t)(tile * TILE_B + row * (KST * 2) + seg * 16), src);
        }
        asm volatile("cp.async.commit_group;" ::: "memory");
    };

    issue(0, 0);
    for (int i = 0; i < 32; i++) {
        if (i > 0) __syncthreads();                  // buf (i+1)&1 free of iter i-1 readers
        if (i + 1 < 32) issue((i + 1) * 32, (i + 1) & 1);
        if (i == 31) asm volatile("cp.async.wait_group 0;" ::: "memory");
        else         asm volatile("cp.async.wait_group 1;" ::: "memory");
        __syncthreads();                             // group-i data visible to all warps

        uint32_t sb = su + (uint32_t)((i & 1) * STAGE_B);
        uint32_t uAh = sb, uAl = sb + TILE_B, uBh = sb + 2 * TILE_B, uBl = sb + 3 * TILE_B;
        #pragma unroll
        for (int kk = 0; kk < 2; kk++) {
            uint32_t kb = (uint32_t)(kk * 32);
            uint32_t ah0[4], ah1[4], al0[4], al1[4];
            ldsm4(ah0[0], ah0[1], ah0[2], ah0[3], uAh + aoff + kb);
            ldsm4(ah1[0], ah1[1], ah1[2], ah1[3], uAh + aoff + kb + 16 * KST * 2);
            ldsm4(al0[0], al0[1], al0[2], al0[3], uAl + aoff + kb);
            ldsm4(al1[0], al1[1], al1[2], al1[3], uAl + aoff + kb + 16 * KST * 2);
            #pragma unroll
            for (int nb = 0; nb < 4; nb++) {
                if (isbc && (wn == 1 || nb >= 2)) continue;   // bc tile: only cols 0..31
                uint32_t bh[4], bl[4];
                uint32_t bo = boff + kb + (uint32_t)(nb * 16 * KST * 2);
                ldsm4(bh[0], bh[1], bh[2], bh[3], uBh + bo);
                ldsm4(bl[0], bl[1], bl[2], bl[3], uBl + bo);
                mma16816(acc[0][2 * nb], ah0, bh[0], bh[1]);
                mma16816(acc[0][2 * nb], ah0, bl[0], bl[1]);
                mma16816(acc[0][2 * nb], al0, bh[0], bh[1]);
                mma16816(acc[1][2 * nb], ah1, bh[0], bh[1]);
                mma16816(acc[1][2 * nb], ah1, bl[0], bl[1]);
                mma16816(acc[1][2 * nb], al1, bh[0], bh[1]);
                mma16816(acc[0][2 * nb + 1], ah0, bh[2], bh[3]);
                mma16816(acc[0][2 * nb + 1], ah0, bl[2], bl[3]);
                mma16816(acc[0][2 * nb + 1], al0, bh[2], bh[3]);
                mma16816(acc[1][2 * nb + 1], ah1, bh[2], bh[3]);
                mma16816(acc[1][2 * nb + 1], ah1, bl[2], bl[3]);
                mma16816(acc[1][2 * nb + 1], al1, bh[2], bh[3]);
            }
        }
    }

    if (!isbc) {
        // epilogue: z -> delta -> (delta, sqrt(delta)*xn)
        const float CTR = 5.00005f, HLF = 4.99995f, INVH = 1.0f / 4.99995f;
        #pragma unroll
        for (int ma = 0; ma < 2; ma++) {
            int row0 = m0 + wm * 32 + ma * 16 + (lane >> 2);
            #pragma unroll
            for (int na = 0; na < 8; na++) {
                int col = n0 + wn * 64 + na * 8 + 2 * (lane & 3);
                float2 bdv = *(const float2*)(bd + col);
                #pragma unroll
                for (int hrow = 0; hrow < 2; hrow++) {
                    int m = row0 + hrow * 8;
                    float z0 = acc[ma][na][2 * hrow]     + bdv.x;
                    float z1 = acc[ma][na][2 * hrow + 1] + bdv.y;
                    float2 xv = *(const float2*)(&g_xn[(size_t)m * D + col]);
                    float sp0 = fmaxf(z0, 0.0f) + log1pf(expf(-fabsf(z0)));
                    float sp1 = fmaxf(z1, 0.0f) + log1pf(expf(-fabsf(z1)));
                    float dl0 = CTR + HLF * tanhf((sp0 - CTR) * INVH);
                    float dl1 = CTR + HLF * tanhf((sp1 - CTR) * INVH);
                    float sx0 = sqrtf(dl0) * xv.x;
                    float sx1 = sqrtf(dl1) * xv.y;
                    *(float2*)(&g_delta[(size_t)m * D + col]) = make_float2(dl0, dl1);
                    *(float2*)(&g_sdx[(size_t)m * D + col])   = make_float2(sx0, sx1);
                }
            }
        }
    } else if (wn == 0) {
        // bc tile epilogue: raw z -> g_bpc[t][0..31]
        #pragma unroll
        for (int ma = 0; ma < 2; ma++) {
            int row0 = m0 + wm * 32 + ma * 16 + (lane >> 2);
            #pragma unroll
            for (int na = 0; na < 4; na++) {
                int col = na * 8 + 2 * (lane & 3);
                #pragma unroll
                for (int hrow = 0; hrow < 2; hrow++) {
                    int m = row0 + hrow * 8;
                    *(float2*)(&g_bpc[(size_t)m * 2 * SN + col]) =
                        make_float2(acc[ma][na][2 * hrow], acc[ma][na][2 * hrow + 1]);
                }
            }
        }
    }
}

// ---------------- kernel 4: chunk-local scan, f32x2 packed ----------------
__global__ __launch_bounds__(128) void k_phase2() {
    int gid = blockIdx.x * 128 + threadIdx.x;   // NC*D threads
    int c = gid >> 10;
    int d = gid & (D - 1);
    const u64 ONE2 = pack2(1.f, 1.f), TWO2 = pack2(2.f, 2.f), NONE2 = pack2(-1.f, -1.f);
    u64 cA2[8], h2[8], P2[8];
    const ulonglong2* ca = (const ulonglong2*)&g_cA[d * SN];
    #pragma unroll
    for (int q = 0; q < 4; q++) {
        ulonglong2 v = ca[q];
        cA2[2 * q] = v.x; cA2[2 * q + 1] = v.y;
    }
    #pragma unroll
    for (int p = 0; p < 8; p++) { h2[p] = 0ull; P2[p] = ONE2; }

    int t0 = c * CT;
    for (int tt = 0; tt < CT; tt++) {
        int t = t0 + tt;
        float dlv = g_delta[(size_t)t * D + d];
        float sdx = g_sdx[(size_t)t * D + d];
        u64 dlv2 = pack2(dlv, dlv), sdx2 = pack2(sdx, sdx);
        const ulonglong2* bp = (const ulonglong2*)&g_bpc[(size_t)t * 2 * SN];
        u64 bp2[8];
        #pragma unroll
        for (int q = 0; q < 4; q++) {
            ulonglong2 v = bp[q];
            bp2[2 * q] = v.x; bp2[2 * q + 1] = v.y;
        }
        #pragma unroll
        for (int p = 0; p < 8; p++) {
            u64 den2 = fma2(cA2[p], dlv2, ONE2);       // 1 + 0.5*delta*|A| > 1
            float2 dd = unpack2(den2);
            u64 dinv2 = pack2(frcp(dd.x), frcp(dd.y));
            u64 ab2 = fma2(dinv2, TWO2, NONE2);        // (1+hf)/(1-hf) = 2*dinv - 1
            u64 bx2 = mul2(mul2(bp2[p], dinv2), sdx2);
            h2[p] = fma2(ab2, h2[p], bx2);
            P2[p] = mul2(P2[p], ab2);
        }
    }
    size_t basei = (size_t)c * (D * SN) + (size_t)d * SN;
    ulonglong2* oP = (ulonglong2*)&g_P[basei];
    ulonglong2* oS = (ulonglong2*)&g_S[basei];
    #pragma unroll
    for (int q = 0; q < 4; q++) {
        ulonglong2 vp, vs;
        vp.x = P2[2 * q]; vp.y = P2[2 * q + 1];
        vs.x = h2[2 * q]; vs.y = h2[2 * q + 1];
        oP[q] = vp; oS[q] = vs;
    }
}

// ---------------- kernel 5: scan over chunk summaries ----------------
__global__ __launch_bounds__(256) void k_phase3() {
    int s = blockIdx.x * 256 + threadIdx.x;  // D*SN threads
    float H = 0.f;
    #pragma unroll 4
    for (int c = 0; c < NC; c++) {
        size_t idx = (size_t)c * (D * SN) + s;
        g_hin[idx] = H;
        H = fmaf(g_P[idx], H, g_S[idx]);
    }
}

// ---------------- kernel 6: recompute with true init, emit y (f32x2) ----------------
__global__ __launch_bounds__(128) void k_phase4(const float* __restrict__ Dskip,
                                                float* __restrict__ y) {
    int gid = blockIdx.x * 128 + threadIdx.x;
    int c = gid >> 10;
    int d = gid & (D - 1);
    const u64 ONE2 = pack2(1.f, 1.f), TWO2 = pack2(2.f, 2.f), NONE2 = pack2(-1.f, -1.f);
    u64 cA2[8], h2[8];
    const ulonglong2* ca = (const ulonglong2*)&g_cA[d * SN];
    #pragma unroll
    for (int q = 0; q < 4; q++) {
        ulonglong2 v = ca[q];
        cA2[2 * q] = v.x; cA2[2 * q + 1] = v.y;
    }
    size_t basei = (size_t)c * (D * SN) + (size_t)d * SN;
    const ulonglong2* hi = (const ulonglong2*)&g_hin[basei];
    #pragma unroll
    for (int q = 0; q < 4; q++) {
        ulonglong2 v = hi[q];
        h2[2 * q] = v.x; h2[2 * q + 1] = v.y;
    }
    float dsk = Dskip[d];

    int t0 = c * CT;
    for (int tt = 0; tt < CT; tt++) {
        int t = t0 + tt;
        float dlv = g_delta[(size_t)t * D + d];
        float sdx = g_sdx[(size_t)t * D + d];
        float xnv = g_xn[(size_t)t * D + d];
        u64 dlv2 = pack2(dlv, dlv), sdx2 = pack2(sdx, sdx);
        const ulonglong2* bc = (const ulonglong2*)&g_bpc[(size_t)t * 2 * SN];
        u64 bp2[8], cc2[8];
        #pragma unroll
        for (int q = 0; q < 4; q++) {
            ulonglong2 vb = bc[q], vc = bc[q + 4];
            bp2[2 * q] = vb.x; bp2[2 * q + 1] = vb.y;
            cc2[2 * q] = vc.x; cc2[2 * q + 1] = vc.y;
        }
        u64 acca = 0ull, accb = 0ull;
        #pragma unroll
        for (int p = 0; p < 8; p++) {
            u64 den2 = fma2(cA2[p], dlv2, ONE2);
            float2 dd = unpack2(den2);
            u64 dinv2 = pack2(frcp(dd.x), frcp(dd.y));
            u64 ab2 = fma2(dinv2, TWO2, NONE2);
            u64 bx2 = mul2(mul2(bp2[p], dinv2), sdx2);
            h2[p] = fma2(ab2, h2[p], bx2);
            if (p & 1) accb = fma2(cc2[p], h2[p], accb);
            else       acca = fma2(cc2[p], h2[p], acca);
        }
        float2 s = unpack2(add2(acca, accb));
        y[(size_t)t * D + d] = fmaf(dsk, xnv, s.x + s.y);
    }
}

// ---------------- launch ----------------
extern "C" void kernel_launch(void* const* d_in, const int* in_sizes, int n_in,
                              void* d_out, int out_size) {
    const float* x       = (const float*)d_in[0];
    const float* A_log   = (const float*)d_in[1];
    const float* W_delta = (const float*)d_in[2];
    const float* b_delta = (const float*)d_in[3];
    const float* W_B     = (const float*)d_in[4];
    const float* W_C     = (const float*)d_in[5];
    const float* D_skip  = (const float*)d_in[6];
    const float* norm_w  = (const float*)d_in[7];
    float* y = (float*)d_out;

    cudaFuncSetAttribute(k_gemm_mma, cudaFuncAttributeMaxDynamicSharedMemorySize,
                         2 * STAGE_B);

    k_prep<<<(D * SN + 255) / 256, 256>>>(A_log);
    k_wt<<<dim3(32, 32), dim3(32, 8)>>>(W_delta);
    k_wbc<<<128 * D / 256, 256>>>(W_B, W_C);
    k_rms<<<L, 256>>>(x, norm_w);
    k_gemm_mma<<<dim3(9, 32), 256, 2 * STAGE_B>>>(b_delta);
    k_phase2<<<NC * D / 128, 128>>>();
    k_phase3<<<D * SN / 256, 256>>>();
    k_phase4<<<NC * D / 128, 128>>>(D_skip, y);
}

// round 7
// speedup vs baseline: 2.8649x; 1.1225x over previous
#include <cuda_runtime.h>
#include <cuda_fp16.h>
#include <math.h>
#include <stdint.h>

// Problem shape (fixed by dataset)
#define L   4096
#define D   1024
#define SN  16
#define NC  64      // number of chunks
#define CT  64      // chunk length; NC*CT == L

typedef unsigned long long u64;

// ---------------- scratch (static device globals; no allocation) ----------------
__device__ float g_xn[L * D];                  // normalized input (fp32)
__device__ __half g_xh[L * D];                 // fp16 hi of xn
__device__ __half g_xl[L * D];                 // fp16 lo of xn
__device__ __half g_wth[D * D];                // W_delta^T fp16 [n][k]
__device__ __half g_wbch[128 * D];             // [WB|WC|0]^T hi [n][k], n<32 real
__device__ __half g_wbcl[128 * D];             // [WB|WC|0]^T lo
__device__ float g_delta[L * D];               // selective delta
__device__ float g_sdx[L * D];                 // sqrt(delta) * xn
__device__ float g_bpc[L * 2 * SN];            // per-t: Bp[0..15], C[16..31]
__device__ float g_cA[D * SN];                 // +0.5*exp(A_log)   (positive!)
__device__ float g_P[NC * D * SN];             // per-chunk product of A_bar
__device__ float g_S[NC * D * SN];             // per-chunk end-state from h0=0
__device__ float g_hin[NC * D * SN];           // per-chunk initial state

// ---------------- helpers ----------------
__device__ __forceinline__ float frcp(float x) {
    float r;
    asm("rcp.approx.f32 %0, %1;" : "=f"(r) : "f"(x));
    return r;
}
__device__ __forceinline__ uint32_t smem_u32(const void* p) {
    uint32_t a;
    asm("{ .reg .u64 t; cvta.to.shared.u64 t, %1; cvt.u32.u64 %0, t; }" : "=r"(a) : "l"(p));
    return a;
}
__device__ __forceinline__ void ldsm4(uint32_t& r0, uint32_t& r1, uint32_t& r2, uint32_t& r3,
                                      uint32_t addr) {
    asm volatile("ldmatrix.sync.aligned.m8n8.x4.shared.b16 {%0,%1,%2,%3}, [%4];"
                 : "=r"(r0), "=r"(r1), "=r"(r2), "=r"(r3) : "r"(addr));
}
__device__ __forceinline__ void mma16816(float* d, const uint32_t* a, uint32_t b0, uint32_t b1) {
    asm volatile(
        "mma.sync.aligned.m16n8k16.row.col.f32.f16.f16.f32 "
        "{%0,%1,%2,%3}, {%4,%5,%6,%7}, {%8,%9}, {%0,%1,%2,%3};"
        : "+f"(d[0]), "+f"(d[1]), "+f"(d[2]), "+f"(d[3])
        : "r"(a[0]), "r"(a[1]), "r"(a[2]), "r"(a[3]), "r"(b0), "r"(b1));
}
__device__ __forceinline__ void cp16(uint32_t dst, const void* src) {
    asm volatile("cp.async.cg.shared.global [%0], [%1], 16;" :: "r"(dst), "l"(src) : "memory");
}
__device__ __forceinline__ u64 pack2(float lo, float hi) {
    u64 r;
    asm("mov.b64 %0, {%1,%2};" : "=l"(r) : "f"(lo), "f"(hi));
    return r;
}
__device__ __forceinline__ float2 unpack2(u64 v) {
    float lo, hi;
    asm("mov.b64 {%0,%1}, %2;" : "=f"(lo), "=f"(hi) : "l"(v));
    return make_float2(lo, hi);
}
__device__ __forceinline__ u64 fma2(u64 a, u64 b, u64 c) {
    u64 d;
    asm("fma.rn.f32x2 %0, %1, %2, %3;" : "=l"(d) : "l"(a), "l"(b), "l"(c));
    return d;
}
__device__ __forceinline__ u64 mul2(u64 a, u64 b) {
    u64 d;
    asm("mul.rn.f32x2 %0, %1, %2;" : "=l"(d) : "l"(a), "l"(b));
    return d;
}
__device__ __forceinline__ u64 add2(u64 a, u64 b) {
    u64 d;
    asm("add.rn.f32x2 %0, %1, %2;" : "=l"(d) : "l"(a), "l"(b));
    return d;
}

// ---------------- kernel 0: cA = +0.5*exp(A_log) ----------------
__global__ void k_prep(const float* __restrict__ A_log) {
    int i = blockIdx.x * blockDim.x + threadIdx.x;
    if (i < D * SN) g_cA[i] = 0.5f * expf(A_log[i]);
}

// ---------------- kernel 0b: transpose W_delta -> fp16 ----------------
__global__ __launch_bounds__(256) void k_wt(const float* __restrict__ W) {
    __shared__ float tile[32][33];
    int bx = blockIdx.x, by = blockIdx.y;
    int tx = threadIdx.x, ty = threadIdx.y;   // 32 x 8
    #pragma unroll
    for (int i = 0; i < 32; i += 8)
        tile[ty + i][tx] = W[(size_t)(by * 32 + ty + i) * D + bx * 32 + tx];
    __syncthreads();
    #pragma unroll
    for (int i = 0; i < 32; i += 8) {
        int n = bx * 32 + ty + i;
        int k = by * 32 + tx;
        g_wth[(size_t)n * D + k] = __float2half(tile[tx][ty + i]);  // = W[k][n]
    }
}

// ---------------- kernel 0c: pack [WB|WC|0]^T, fp16 hi/lo split ----------------
__global__ __launch_bounds__(256) void k_wbc(const float* __restrict__ WB,
                                             const float* __restrict__ WC) {
    int idx = blockIdx.x * 256 + threadIdx.x;   // 128*1024
    int n = idx >> 10, k = idx & 1023;
    float v = 0.f;
    if (n < SN) v = WB[(size_t)k * SN + n];
    else if (n < 2 * SN) v = WC[(size_t)k * SN + n - SN];
    __half h = __float2half(v);
    __half l = __float2half(v - __half2float(h));
    g_wbch[idx] = h;
    g_wbcl[idx] = l;
}

// ---------------- kernel 1: RMSNorm (+ fp16 hi/lo split of xn) ----------------
__global__ __launch_bounds__(256) void k_rms(const float* __restrict__ x,
                                             const float* __restrict__ w) {
    int row = blockIdx.x;
    int tid = threadIdx.x;
    const float4 xv = *(const float4*)(x + (size_t)row * D + tid * 4);
    float s = xv.x * xv.x + xv.y * xv.y + xv.z * xv.z + xv.w * xv.w;
    #pragma unroll
    for (int o = 16; o > 0; o >>= 1) s += __shfl_xor_sync(0xFFFFFFFFu, s, o);
    __shared__ float red[8];
    int warp = tid >> 5, lane = tid & 31;
    if (lane == 0) red[warp] = s;
    __syncthreads();
    float tot = 0.f;
    #pragma unroll
    for (int i = 0; i < 8; i++) tot += red[i];
    float inv = 1.0f / sqrtf(tot * (1.0f / (float)D) + 1e-6f);
    const float4 wv = *(const float4*)(w + tid * 4);
    float4 o;
    o.x = wv.x * xv.x * inv;
    o.y = wv.y * xv.y * inv;
    o.z = wv.z * xv.z * inv;
    o.w = wv.w * xv.w * inv;
    size_t base = (size_t)row * D + tid * 4;
    *(float4*)(&g_xn[base]) = o;
    float vv[4] = {o.x, o.y, o.z, o.w};
    __half hh[4], ll[4];
    #pragma unroll
    for (int i = 0; i < 4; i++) {
        hh[i] = __float2half(vv[i]);
        ll[i] = __float2half(vv[i] - __half2float(hh[i]));
    }
    ((__half2*)(&g_xh[base]))[0] = __halves2half2(hh[0], hh[1]);
    ((__half2*)(&g_xh[base]))[1] = __halves2half2(hh[2], hh[3]);
    ((__half2*)(&g_xl[base]))[0] = __halves2half2(ll[0], ll[1]);
    ((__half2*)(&g_xl[base]))[1] = __halves2half2(ll[2], ll[3]);
}

// ---------------- kernel 3: fused GEMM (delta + Bp/C) via mma.sync fp16 ----------------
// grid (9, 32): bn<8 -> Z=xn@W_delta (2-term: Ah*B + Al*B); bn==8 -> [Bp|C] (3-term).
// CTA tile 128x128, 8 warps each 32(m) x 64(n). cp.async 2-stage pipeline.
#define KST 40                       // smem row stride in fp16 (80B)
#define TILE_B (128 * KST * 2)       // 10240 B per tile
#define STAGE_B (4 * TILE_B)         // 40960 B per stage (tile3 = Bl, bc only)
__global__ __launch_bounds__(256, 2) void k_gemm_mma(const float* __restrict__ bd) {
    extern __shared__ __align__(16) char smem[];
    const uint32_t su = smem_u32(smem);

    int tid = threadIdx.x, wid = tid >> 5, lane = tid & 31;
    int bm = blockIdx.y, bn = blockIdx.x;
    const bool isbc = (bn == 8);
    const int m0 = bm * 128, n0 = bn * 128;
    int wm = wid & 3, wn = wid >> 2;

    const __half* pA0 = g_xh + (size_t)m0 * D;
    const __half* pA1 = g_xl + (size_t)m0 * D;
    const __half* pB0 = isbc ? g_wbch : g_wth + (size_t)n0 * D;
    const __half* pB1 = g_wbcl;   // only consumed when isbc

    float acc[2][8][4];
    #pragma unroll
    for (int a = 0; a < 2; a++)
        #pragma unroll
        for (int b = 0; b < 8; b++)
            #pragma unroll
            for (int c = 0; c < 4; c++) acc[a][b][c] = 0.f;

    // ldmatrix per-lane offsets (within a stage)
    uint32_t aoff = (uint32_t)((wm * 32 + (lane & 15)) * (KST * 2) + ((lane >> 4) << 4));
    uint32_t boff = (uint32_t)((wn * 64 + (lane & 7) + ((lane >> 4) << 3)) * (KST * 2) +
                               (((lane >> 3) & 1) << 4));

    auto issue = [&](int k0, int stage) {
        uint32_t sb = su + (uint32_t)(stage * STAGE_B);
        #pragma unroll
        for (int j = 0; j < 8; j++) {
            const int tile = j >> 1;
            if (tile == 3 && !isbc) continue;       // delta CTAs: 3 tiles only
            int sub = tid + (j & 1) * 256;          // 0..511
            int row = sub >> 2, seg = sub & 3;
            const __half* src;
            if (tile == 0)      src = pA0 + (size_t)row * D + k0 + seg * 8;
            else if (tile == 1) src = pA1 + (size_t)row * D + k0 + seg * 8;
            else if (tile == 2) src = pB0 + (size_t)row * D + k0 + seg * 8;
            else                src = pB1 + (size_t)row * D + k0 + seg * 8;
            cp16(sb + (uint32_t)(tile * TILE_B + row * (KST * 2) + seg * 16), src);
        }
        asm volatile("cp.async.commit_group;" ::: "memory");
    };

    issue(0, 0);
    for (int i = 0; i < 32; i++) {
        if (i > 0) __syncthreads();
        if (i + 1 < 32) issue((i + 1) * 32, (i + 1) & 1);
        if (i == 31) asm volatile("cp.async.wait_group 0;" ::: "memory");
        else         asm volatile("cp.async.wait_group 1;" ::: "memory");
        __syncthreads();

        uint32_t sb = su + (uint32_t)((i & 1) * STAGE_B);
        uint32_t uAh = sb, uAl = sb + TILE_B, uBh = sb + 2 * TILE_B, uBl = sb + 3 * TILE_B;
        #pragma unroll
        for (int kk = 0; kk < 2; kk++) {
            uint32_t kb = (uint32_t)(kk * 32);
            uint32_t ah0[4], ah1[4], al0[4], al1[4];
            ldsm4(ah0[0], ah0[1], ah0[2], ah0[3], uAh + aoff + kb);
            ldsm4(ah1[0], ah1[1], ah1[2], ah1[3], uAh + aoff + kb + 16 * KST * 2);
            ldsm4(al0[0], al0[1], al0[2], al0[3], uAl + aoff + kb);
            ldsm4(al1[0], al1[1], al1[2], al1[3], uAl + aoff + kb + 16 * KST * 2);
            #pragma unroll
            for (int nb = 0; nb < 4; nb++) {
                if (isbc && (wn == 1 || nb >= 2)) continue;   // bc: only cols 0..31
                uint32_t bh[4];
                uint32_t bo = boff + kb + (uint32_t)(nb * 16 * KST * 2);
                ldsm4(bh[0], bh[1], bh[2], bh[3], uBh + bo);
                mma16816(acc[0][2 * nb],     ah0, bh[0], bh[1]);
                mma16816(acc[0][2 * nb],     al0, bh[0], bh[1]);
                mma16816(acc[1][2 * nb],     ah1, bh[0], bh[1]);
                mma16816(acc[1][2 * nb],     al1, bh[0], bh[1]);
                mma16816(acc[0][2 * nb + 1], ah0, bh[2], bh[3]);
                mma16816(acc[0][2 * nb + 1], al0, bh[2], bh[3]);
                mma16816(acc[1][2 * nb + 1], ah1, bh[2], bh[3]);
                mma16816(acc[1][2 * nb + 1], al1, bh[2], bh[3]);
                if (isbc) {
                    uint32_t bl[4];
                    ldsm4(bl[0], bl[1], bl[2], bl[3], uBl + bo);
                    mma16816(acc[0][2 * nb],     ah0, bl[0], bl[1]);
                    mma16816(acc[1][2 * nb],     ah1, bl[0], bl[1]);
                    mma16816(acc[0][2 * nb + 1], ah0, bl[2], bl[3]);
                    mma16816(acc[1][2 * nb + 1], ah1, bl[2], bl[3]);
                }
            }
        }
    }

    if (!isbc) {
        // epilogue: z -> delta -> (delta, sqrt(delta)*xn)
        const float CTR = 5.00005f, HLF = 4.99995f, INVH = 1.0f / 4.99995f;
        #pragma unroll
        for (int ma = 0; ma < 2; ma++) {
            int row0 = m0 + wm * 32 + ma * 16 + (lane >> 2);
            #pragma unroll
            for (int na = 0; na < 8; na++) {
                int col = n0 + wn * 64 + na * 8 + 2 * (lane & 3);
                float2 bdv = *(const float2*)(bd + col);
                #pragma unroll
                for (int hrow = 0; hrow < 2; hrow++) {
                    int m = row0 + hrow * 8;
                    float z0 = acc[ma][na][2 * hrow]     + bdv.x;
                    float z1 = acc[ma][na][2 * hrow + 1] + bdv.y;
                    float2 xv = *(const float2*)(&g_xn[(size_t)m * D + col]);
                    float sp0 = fmaxf(z0, 0.0f) + log1pf(expf(-fabsf(z0)));
                    float sp1 = fmaxf(z1, 0.0f) + log1pf(expf(-fabsf(z1)));
                    float dl0 = CTR + HLF * tanhf((sp0 - CTR) * INVH);
                    float dl1 = CTR + HLF * tanhf((sp1 - CTR) * INVH);
                    float sx0 = sqrtf(dl0) * xv.x;
                    float sx1 = sqrtf(dl1) * xv.y;
                    *(float2*)(&g_delta[(size_t)m * D + col]) = make_float2(dl0, dl1);
                    *(float2*)(&g_sdx[(size_t)m * D + col])   = make_float2(sx0, sx1);
                }
            }
        }
    } else if (wn == 0) {
        // bc tile epilogue: raw z -> g_bpc[t][0..31]
        #pragma unroll
        for (int ma = 0; ma < 2; ma++) {
            int row0 = m0 + wm * 32 + ma * 16 + (lane >> 2);
            #pragma unroll
            for (int na = 0; na < 4; na++) {
                int col = na * 8 + 2 * (lane & 3);
                #pragma unroll
                for (int hrow = 0; hrow < 2; hrow++) {
                    int m = row0 + hrow * 8;
                    *(float2*)(&g_bpc[(size_t)m * 2 * SN + col]) =
                        make_float2(acc[ma][na][2 * hrow], acc[ma][na][2 * hrow + 1]);
                }
            }
        }
    }
}

// ---------------- kernel 4: chunk-local scan, f32x2 packed ----------------
__global__ __launch_bounds__(128) void k_phase2() {
    int gid = blockIdx.x * 128 + threadIdx.x;   // NC*D threads
    int c = gid >> 10;
    int d = gid & (D - 1);
    const u64 ONE2 = pack2(1.f, 1.f), TWO2 = pack2(2.f, 2.f), NONE2 = pack2(-1.f, -1.f);
    u64 cA2[8], h2[8], P2[8];
    const ulonglong2* ca = (const ulonglong2*)&g_cA[d * SN];
    #pragma unroll
    for (int q = 0; q < 4; q++) {
        ulonglong2 v = ca[q];
        cA2[2 * q] = v.x; cA2[2 * q + 1] = v.y;
    }
    #pragma unroll
    for (int p = 0; p < 8; p++) { h2[p] = 0ull; P2[p] = ONE2; }

    int t0 = c * CT;
    for (int tt = 0; tt < CT; tt++) {
        int t = t0 + tt;
        float dlv = g_delta[(size_t)t * D + d];
        float sdx = g_sdx[(size_t)t * D + d];
        u64 dlv2 = pack2(dlv, dlv), sdx2 = pack2(sdx, sdx);
        const ulonglong2* bp = (const ulonglong2*)&g_bpc[(size_t)t * 2 * SN];
        u64 bp2[8];
        #pragma unroll
        for (int q = 0; q < 4; q++) {
            ulonglong2 v = bp[q];
            bp2[2 * q] = v.x; bp2[2 * q + 1] = v.y;
        }
        #pragma unroll
        for (int p = 0; p < 8; p++) {
            u64 den2 = fma2(cA2[p], dlv2, ONE2);       // 1 + 0.5*delta*|A| > 1
            float2 dd = unpack2(den2);
            u64 dinv2 = pack2(frcp(dd.x), frcp(dd.y));
            u64 ab2 = fma2(dinv2, TWO2, NONE2);        // (1+hf)/(1-hf) = 2*dinv - 1
            u64 bx2 = mul2(mul2(bp2[p], dinv2), sdx2);
            h2[p] = fma2(ab2, h2[p], bx2);
            P2[p] = mul2(P2[p], ab2);
        }
    }
    size_t basei = (size_t)c * (D * SN) + (size_t)d * SN;
    ulonglong2* oP = (ulonglong2*)&g_P[basei];
    ulonglong2* oS = (ulonglong2*)&g_S[basei];
    #pragma unroll
    for (int q = 0; q < 4; q++) {
        ulonglong2 vp, vs;
        vp.x = P2[2 * q]; vp.y = P2[2 * q + 1];
        vs.x = h2[2 * q]; vs.y = h2[2 * q + 1];
        oP[q] = vp; oS[q] = vs;
    }
}

// ---------------- kernel 5: scan over chunk summaries ----------------
__global__ __launch_bounds__(256) void k_phase3() {
    int s = blockIdx.x * 256 + threadIdx.x;  // D*SN threads
    float H = 0.f;
    #pragma unroll 4
    for (int c = 0; c < NC; c++) {
        size_t idx = (size_t)c * (D * SN) + s;
        g_hin[idx] = H;
        H = fmaf(g_P[idx], H, g_S[idx]);
    }
}

// ---------------- kernel 6: recompute with true init, emit y (f32x2) ----------------
__global__ __launch_bounds__(128) void k_phase4(const float* __restrict__ Dskip,
                                                float* __restrict__ y) {
    int gid = blockIdx.x * 128 + threadIdx.x;
    int c = gid >> 10;
    int d = gid & (D - 1);
    const u64 ONE2 = pack2(1.f, 1.f), TWO2 = pack2(2.f, 2.f), NONE2 = pack2(-1.f, -1.f);
    u64 cA2[8], h2[8];
    const ulonglong2* ca = (const ulonglong2*)&g_cA[d * SN];
    #pragma unroll
    for (int q = 0; q < 4; q++) {
        ulonglong2 v = ca[q];
        cA2[2 * q] = v.x; cA2[2 * q + 1] = v.y;
    }
    size_t basei = (size_t)c * (D * SN) + (size_t)d * SN;
    const ulonglong2* hi = (const ulonglong2*)&g_hin[basei];
    #pragma unroll
    for (int q = 0; q < 4; q++) {
        ulonglong2 v = hi[q];
        h2[2 * q] = v.x; h2[2 * q + 1] = v.y;
    }
    float dsk = Dskip[d];

    int t0 = c * CT;
    for (int tt = 0; tt < CT; tt++) {
        int t = t0 + tt;
        float dlv = g_delta[(size_t)t * D + d];
        float sdx = g_sdx[(size_t)t * D + d];
        float xnv = g_xn[(size_t)t * D + d];
        u64 dlv2 = pack2(dlv, dlv), sdx2 = pack2(sdx, sdx);
        const ulonglong2* bc = (const ulonglong2*)&g_bpc[(size_t)t * 2 * SN];
        u64 bp2[8], cc2[8];
        #pragma unroll
        for (int q = 0; q < 4; q++) {
            ulonglong2 vb = bc[q], vc = bc[q + 4];
            bp2[2 * q] = vb.x; bp2[2 * q + 1] = vb.y;
            cc2[2 * q] = vc.x; cc2[2 * q + 1] = vc.y;
        }
        u64 acca = 0ull, accb = 0ull;
        #pragma unroll
        for (int p = 0; p < 8; p++) {
            u64 den2 = fma2(cA2[p], dlv2, ONE2);
            float2 dd = unpack2(den2);
            u64 dinv2 = pack2(frcp(dd.x), frcp(dd.y));
            u64 ab2 = fma2(dinv2, TWO2, NONE2);
            u64 bx2 = mul2(mul2(bp2[p], dinv2), sdx2);
            h2[p] = fma2(ab2, h2[p], bx2);
            if (p & 1) accb = fma2(cc2[p], h2[p], accb);
            else       acca = fma2(cc2[p], h2[p], acca);
        }
        float2 s = unpack2(add2(acca, accb));
        y[(size_t)t * D + d] = fmaf(dsk, xnv, s.x + s.y);
    }
}

// ---------------- launch ----------------
extern "C" void kernel_launch(void* const* d_in, const int* in_sizes, int n_in,
                              void* d_out, int out_size) {
    const float* x       = (const float*)d_in[0];
    const float* A_log   = (const float*)d_in[1];
    const float* W_delta = (const float*)d_in[2];
    const float* b_delta = (const float*)d_in[3];
    const float* W_B     = (const float*)d_in[4];
    const float* W_C     = (const float*)d_in[5];
    const float* D_skip  = (const float*)d_in[6];
    const float* norm_w  = (const float*)d_in[7];
    float* y = (float*)d_out;

    cudaFuncSetAttribute(k_gemm_mma, cudaFuncAttributeMaxDynamicSharedMemorySize,
                         2 * STAGE_B);

    k_prep<<<(D * SN + 255) / 256, 256>>>(A_log);
    k_wt<<<dim3(32, 32), dim3(32, 8)>>>(W_delta);
    k_wbc<<<128 * D / 256, 256>>>(W_B, W_C);
    k_rms<<<L, 256>>>(x, norm_w);
    k_gemm_mma<<<dim3(9, 32), 256, 2 * STAGE_B>>>(b_delta);
    k_phase2<<<NC * D / 128, 128>>>();
    k_phase3<<<D * SN / 256, 256>>>();
    k_phase4<<<NC * D / 128, 128>>>(D_skip, y);
}

// round 8
// speedup vs baseline: 3.1076x; 1.0847x over previous
#include <cuda_runtime.h>
#include <cuda_fp16.h>
#include <math.h>
#include <stdint.h>

// Problem shape (fixed by dataset)
#define L   4096
#define D   1024
#define SN  16
#define NC  64      // number of chunks
#define CT  64      // chunk length; NC*CT == L

typedef unsigned long long u64;

// ---------------- scratch (static device globals; no allocation) ----------------
__device__ float g_xn[L * D];                  // normalized input (fp32)
__device__ __half g_xh[L * D];                 // fp16 hi of xn
__device__ __half g_xl[L * D];                 // fp16 lo of xn (bc tile only)
__device__ __half g_wth[D * D];                // W_delta^T fp16 [n][k]
__device__ __half g_wbch[128 * D];             // [WB|WC|0]^T hi [n][k], n<32 real
__device__ __half g_wbcl[128 * D];             // [WB|WC|0]^T lo
__device__ float g_delta[L * D];               // selective delta
__device__ float g_sdx[L * D];                 // sqrt(delta) * xn
__device__ float g_bpc[L * 2 * SN];            // per-t: Bp[0..15], C[16..31]
__device__ float g_cA[D * SN];                 // +0.5*exp(A_log)   (positive!)
__device__ float g_P[NC * D * SN];             // per-chunk product of A_bar
__device__ float g_S[NC * D * SN];             // per-chunk end-state from h0=0
__device__ float g_hin[NC * D * SN];           // per-chunk initial state

// ---------------- helpers ----------------
__device__ __forceinline__ float frcp(float x) {
    float r;
    asm("rcp.approx.f32 %0, %1;" : "=f"(r) : "f"(x));
    return r;
}
__device__ __forceinline__ uint32_t smem_u32(const void* p) {
    uint32_t a;
    asm("{ .reg .u64 t; cvta.to.shared.u64 t, %1; cvt.u32.u64 %0, t; }" : "=r"(a) : "l"(p));
    return a;
}
__device__ __forceinline__ void ldsm4(uint32_t& r0, uint32_t& r1, uint32_t& r2, uint32_t& r3,
                                      uint32_t addr) {
    asm volatile("ldmatrix.sync.aligned.m8n8.x4.shared.b16 {%0,%1,%2,%3}, [%4];"
                 : "=r"(r0), "=r"(r1), "=r"(r2), "=r"(r3) : "r"(addr));
}
__device__ __forceinline__ void mma16816(float* d, const uint32_t* a, uint32_t b0, uint32_t b1) {
    asm volatile(
        "mma.sync.aligned.m16n8k16.row.col.f32.f16.f16.f32 "
        "{%0,%1,%2,%3}, {%4,%5,%6,%7}, {%8,%9}, {%0,%1,%2,%3};"
        : "+f"(d[0]), "+f"(d[1]), "+f"(d[2]), "+f"(d[3])
        : "r"(a[0]), "r"(a[1]), "r"(a[2]), "r"(a[3]), "r"(b0), "r"(b1));
}
__device__ __forceinline__ void cp16(uint32_t dst, const void* src) {
    asm volatile("cp.async.cg.shared.global [%0], [%1], 16;" :: "r"(dst), "l"(src) : "memory");
}
__device__ __forceinline__ u64 pack2(float lo, float hi) {
    u64 r;
    asm("mov.b64 %0, {%1,%2};" : "=l"(r) : "f"(lo), "f"(hi));
    return r;
}
__device__ __forceinline__ float2 unpack2(u64 v) {
    float lo, hi;
    asm("mov.b64 {%0,%1}, %2;" : "=f"(lo), "=f"(hi) : "l"(v));
    return make_float2(lo, hi);
}
__device__ __forceinline__ u64 fma2(u64 a, u64 b, u64 c) {
    u64 d;
    asm("fma.rn.f32x2 %0, %1, %2, %3;" : "=l"(d) : "l"(a), "l"(b), "l"(c));
    return d;
}
__device__ __forceinline__ u64 mul2(u64 a, u64 b) {
    u64 d;
    asm("mul.rn.f32x2 %0, %1, %2;" : "=l"(d) : "l"(a), "l"(b));
    return d;
}
__device__ __forceinline__ u64 add2(u64 a, u64 b) {
    u64 d;
    asm("add.rn.f32x2 %0, %1, %2;" : "=l"(d) : "l"(a), "l"(b));
    return d;
}

// ---------------- kernel 0: cA = +0.5*exp(A_log) ----------------
__global__ void k_prep(const float* __restrict__ A_log) {
    int i = blockIdx.x * blockDim.x + threadIdx.x;
    if (i < D * SN) g_cA[i] = 0.5f * expf(A_log[i]);
}

// ---------------- kernel 0b: transpose W_delta -> fp16 ----------------
__global__ __launch_bounds__(256) void k_wt(const float* __restrict__ W) {
    __shared__ float tile[32][33];
    int bx = blockIdx.x, by = blockIdx.y;
    int tx = threadIdx.x, ty = threadIdx.y;   // 32 x 8
    #pragma unroll
    for (int i = 0; i < 32; i += 8)
        tile[ty + i][tx] = W[(size_t)(by * 32 + ty + i) * D + bx * 32 + tx];
    __syncthreads();
    #pragma unroll
    for (int i = 0; i < 32; i += 8) {
        int n = bx * 32 + ty + i;
        int k = by * 32 + tx;
        g_wth[(size_t)n * D + k] = __float2half(tile[tx][ty + i]);  // = W[k][n]
    }
}

// ---------------- kernel 0c: pack [WB|WC|0]^T, fp16 hi/lo split ----------------
__global__ __launch_bounds__(256) void k_wbc(const float* __restrict__ WB,
                                             const float* __restrict__ WC) {
    int idx = blockIdx.x * 256 + threadIdx.x;   // 128*1024
    int n = idx >> 10, k = idx & 1023;
    float v = 0.f;
    if (n < SN) v = WB[(size_t)k * SN + n];
    else if (n < 2 * SN) v = WC[(size_t)k * SN + n - SN];
    __half h = __float2half(v);
    __half l = __float2half(v - __half2float(h));
    g_wbch[idx] = h;
    g_wbcl[idx] = l;
}

// ---------------- kernel 1: RMSNorm (+ fp16 hi/lo split of xn) ----------------
__global__ __launch_bounds__(256) void k_rms(const float* __restrict__ x,
                                             const float* __restrict__ w) {
    int row = blockIdx.x;
    int tid = threadIdx.x;
    const float4 xv = *(const float4*)(x + (size_t)row * D + tid * 4);
    float s = xv.x * xv.x + xv.y * xv.y + xv.z * xv.z + xv.w * xv.w;
    #pragma unroll
    for (int o = 16; o > 0; o >>= 1) s += __shfl_xor_sync(0xFFFFFFFFu, s, o);
    __shared__ float red[8];
    int warp = tid >> 5, lane = tid & 31;
    if (lane == 0) red[warp] = s;
    __syncthreads();
    float tot = 0.f;
    #pragma unroll
    for (int i = 0; i < 8; i++) tot += red[i];
    float inv = 1.0f / sqrtf(tot * (1.0f / (float)D) + 1e-6f);
    const float4 wv = *(const float4*)(w + tid * 4);
    float4 o;
    o.x = wv.x * xv.x * inv;
    o.y = wv.y * xv.y * inv;
    o.z = wv.z * xv.z * inv;
    o.w = wv.w * xv.w * inv;
    size_t base = (size_t)row * D + tid * 4;
    *(float4*)(&g_xn[base]) = o;
    float vv[4] = {o.x, o.y, o.z, o.w};
    __half hh[4], ll[4];
    #pragma unroll
    for (int i = 0; i < 4; i++) {
        hh[i] = __float2half(vv[i]);
        ll[i] = __float2half(vv[i] - __half2float(hh[i]));
    }
    ((__half2*)(&g_xh[base]))[0] = __halves2half2(hh[0], hh[1]);
    ((__half2*)(&g_xh[base]))[1] = __halves2half2(hh[2], hh[3]);
    ((__half2*)(&g_xl[base]))[0] = __halves2half2(ll[0], ll[1]);
    ((__half2*)(&g_xl[base]))[1] = __halves2half2(ll[2], ll[3]);
}

// ---------------- kernel 3: fused GEMM (delta + Bp/C) via mma.sync fp16 ----------------
// grid (9, 32): bn<8 -> Z=xn@W_delta (1-term: Ah*B); bn==8 -> [Bp|C] (3-term hi/lo).
// CTA tile 128x128, 8 warps each 32(m) x 64(n). cp.async 2-stage pipeline.
#define KST 40                       // smem row stride in fp16 (80B)
#define TILE_B (128 * KST * 2)       // 10240 B per tile
#define STAGE_B (4 * TILE_B)         // 40960 B per stage (tiles 1,3 = bc only)
__global__ __launch_bounds__(256, 2) void k_gemm_mma(const float* __restrict__ bd) {
    extern __shared__ __align__(16) char smem[];
    const uint32_t su = smem_u32(smem);

    int tid = threadIdx.x, wid = tid >> 5, lane = tid & 31;
    int bm = blockIdx.y, bn = blockIdx.x;
    const bool isbc = (bn == 8);
    const int m0 = bm * 128, n0 = bn * 128;
    int wm = wid & 3, wn = wid >> 2;

    const __half* pA0 = g_xh + (size_t)m0 * D;
    const __half* pA1 = g_xl + (size_t)m0 * D;   // bc only
    const __half* pB0 = isbc ? g_wbch : g_wth + (size_t)n0 * D;
    const __half* pB1 = g_wbcl;                  // bc only

    float acc[2][8][4];
    #pragma unroll
    for (int a = 0; a < 2; a++)
        #pragma unroll
        for (int b = 0; b < 8; b++)
            #pragma unroll
            for (int c = 0; c < 4; c++) acc[a][b][c] = 0.f;

    // ldmatrix per-lane offsets (within a stage)
    uint32_t aoff = (uint32_t)((wm * 32 + (lane & 15)) * (KST * 2) + ((lane >> 4) << 4));
    uint32_t boff = (uint32_t)((wn * 64 + (lane & 7) + ((lane >> 4) << 3)) * (KST * 2) +
                               (((lane >> 3) & 1) << 4));

    auto issue = [&](int k0, int stage) {
        uint32_t sb = su + (uint32_t)(stage * STAGE_B);
        #pragma unroll
        for (int j = 0; j < 8; j++) {
            const int tile = j >> 1;
            if ((tile == 1 || tile == 3) && !isbc) continue;  // delta: Ah + B only
            int sub = tid + (j & 1) * 256;          // 0..511
            int row = sub >> 2, seg = sub & 3;
            const __half* src;
            if (tile == 0)      src = pA0 + (size_t)row * D + k0 + seg * 8;
            else if (tile == 1) src = pA1 + (size_t)row * D + k0 + seg * 8;
            else if (tile == 2) src = pB0 + (size_t)row * D + k0 + seg * 8;
            else                src = pB1 + (size_t)row * D + k0 + seg * 8;
            cp16(sb + (uint32_t)(tile * TILE_B + row * (KST * 2) + seg * 16), src);
        }
        asm volatile("cp.async.commit_group;" ::: "memory");
    };

    issue(0, 0);
    for (int i = 0; i < 32; i++) {
        if (i > 0) __syncthreads();
        if (i + 1 < 32) issue((i + 1) * 32, (i + 1) & 1);
        if (i == 31) asm volatile("cp.async.wait_group 0;" ::: "memory");
        else         asm volatile("cp.async.wait_group 1;" ::: "memory");
        __syncthreads();

        uint32_t sb = su + (uint32_t)((i & 1) * STAGE_B);
        uint32_t uAh = sb, uAl = sb + TILE_B, uBh = sb + 2 * TILE_B, uBl = sb + 3 * TILE_B;
        #pragma unroll
        for (int kk = 0; kk < 2; kk++) {
            uint32_t kb = (uint32_t)(kk * 32);
            uint32_t ah0[4], ah1[4];
            ldsm4(ah0[0], ah0[1], ah0[2], ah0[3], uAh + aoff + kb);
            ldsm4(ah1[0], ah1[1], ah1[2], ah1[3], uAh + aoff + kb + 16 * KST * 2);
            #pragma unroll
            for (int nb = 0; nb < 4; nb++) {
                if (isbc && (wn == 1 || nb >= 2)) continue;   // bc: only cols 0..31
                uint32_t bh[4];
                uint32_t bo = boff + kb + (uint32_t)(nb * 16 * KST * 2);
                ldsm4(bh[0], bh[1], bh[2], bh[3], uBh + bo);
                mma16816(acc[0][2 * nb],     ah0, bh[0], bh[1]);
                mma16816(acc[1][2 * nb],     ah1, bh[0], bh[1]);
                mma16816(acc[0][2 * nb + 1], ah0, bh[2], bh[3]);
                mma16816(acc[1][2 * nb + 1], ah1, bh[2], bh[3]);
                if (isbc) {
                    uint32_t al0[4], al1[4], bl[4];
                    ldsm4(al0[0], al0[1], al0[2], al0[3], uAl + aoff + kb);
                    ldsm4(al1[0], al1[1], al1[2], al1[3], uAl + aoff + kb + 16 * KST * 2);
                    ldsm4(bl[0], bl[1], bl[2], bl[3], uBl + bo);
                    mma16816(acc[0][2 * nb],     al0, bh[0], bh[1]);
                    mma16816(acc[1][2 * nb],     al1, bh[0], bh[1]);
                    mma16816(acc[0][2 * nb + 1], al0, bh[2], bh[3]);
                    mma16816(acc[1][2 * nb + 1], al1, bh[2], bh[3]);
                    mma16816(acc[0][2 * nb],     ah0, bl[0], bl[1]);
                    mma16816(acc[1][2 * nb],     ah1, bl[0], bl[1]);
                    mma16816(acc[0][2 * nb + 1], ah0, bl[2], bl[3]);
                    mma16816(acc[1][2 * nb + 1], ah1, bl[2], bl[3]);
                }
            }
        }
    }

    if (!isbc) {
        // epilogue: z -> delta -> (delta, sqrt(delta)*xn)
        const float CTR = 5.00005f, HLF = 4.99995f, INVH = 1.0f / 4.99995f;
        #pragma unroll
        for (int ma = 0; ma < 2; ma++) {
            int row0 = m0 + wm * 32 + ma * 16 + (lane >> 2);
            #pragma unroll
            for (int na = 0; na < 8; na++) {
                int col = n0 + wn * 64 + na * 8 + 2 * (lane & 3);
                float2 bdv = *(const float2*)(bd + col);
                #pragma unroll
                for (int hrow = 0; hrow < 2; hrow++) {
                    int m = row0 + hrow * 8;
                    float z0 = acc[ma][na][2 * hrow]     + bdv.x;
                    float z1 = acc[ma][na][2 * hrow + 1] + bdv.y;
                    float2 xv = *(const float2*)(&g_xn[(size_t)m * D + col]);
                    float sp0 = fmaxf(z0, 0.0f) + log1pf(expf(-fabsf(z0)));
                    float sp1 = fmaxf(z1, 0.0f) + log1pf(expf(-fabsf(z1)));
                    float dl0 = CTR + HLF * tanhf((sp0 - CTR) * INVH);
                    float dl1 = CTR + HLF * tanhf((sp1 - CTR) * INVH);
                    float sx0 = sqrtf(dl0) * xv.x;
                    float sx1 = sqrtf(dl1) * xv.y;
                    *(float2*)(&g_delta[(size_t)m * D + col]) = make_float2(dl0, dl1);
                    *(float2*)(&g_sdx[(size_t)m * D + col])   = make_float2(sx0, sx1);
                }
            }
        }
    } else if (wn == 0) {
        // bc tile epilogue: raw z -> g_bpc[t][0..31]
        #pragma unroll
        for (int ma = 0; ma < 2; ma++) {
            int row0 = m0 + wm * 32 + ma * 16 + (lane >> 2);
            #pragma unroll
            for (int na = 0; na < 4; na++) {
                int col = na * 8 + 2 * (lane & 3);
                #pragma unroll
                for (int hrow = 0; hrow < 2; hrow++) {
                    int m = row0 + hrow * 8;
                    *(float2*)(&g_bpc[(size_t)m * 2 * SN + col]) =
                        make_float2(acc[ma][na][2 * hrow], acc[ma][na][2 * hrow + 1]);
                }
            }
        }
    }
}

// ---------------- kernel 4: chunk-local scan, f32x2 packed ----------------
__global__ __launch_bounds__(128) void k_phase2() {
    int gid = blockIdx.x * 128 + threadIdx.x;   // NC*D threads
    int c = gid >> 10;
    int d = gid & (D - 1);
    const u64 ONE2 = pack2(1.f, 1.f), TWO2 = pack2(2.f, 2.f), NONE2 = pack2(-1.f, -1.f);
    u64 cA2[8], h2[8], P2[8];
    const ulonglong2* ca = (const ulonglong2*)&g_cA[d * SN];
    #pragma unroll
    for (int q = 0; q < 4; q++) {
        ulonglong2 v = ca[q];
        cA2[2 * q] = v.x; cA2[2 * q + 1] = v.y;
    }
    #pragma unroll
    for (int p = 0; p < 8; p++) { h2[p] = 0ull; P2[p] = ONE2; }

    int t0 = c * CT;
    for (int tt = 0; tt < CT; tt++) {
        int t = t0 + tt;
        float dlv = g_delta[(size_t)t * D + d];
        float sdx = g_sdx[(size_t)t * D + d];
        u64 dlv2 = pack2(dlv, dlv), sdx2 = pack2(sdx, sdx);
        const ulonglong2* bp = (const ulonglong2*)&g_bpc[(size_t)t * 2 * SN];
        u64 bp2[8];
        #pragma unroll
        for (int q = 0; q < 4; q++) {
            ulonglong2 v = bp[q];
            bp2[2 * q] = v.x; bp2[2 * q + 1] = v.y;
        }
        #pragma unroll
        for (int p = 0; p < 8; p++) {
            u64 den2 = fma2(cA2[p], dlv2, ONE2);       // 1 + 0.5*delta*|A| > 1
            float2 dd = unpack2(den2);
            u64 dinv2 = pack2(frcp(dd.x), frcp(dd.y));
            u64 ab2 = fma2(dinv2, TWO2, NONE2);        // (1+hf)/(1-hf) = 2*dinv - 1
            u64 bx2 = mul2(mul2(bp2[p], dinv2), sdx2);
            h2[p] = fma2(ab2, h2[p], bx2);
            P2[p] = mul2(P2[p], ab2);
        }
    }
    size_t basei = (size_t)c * (D * SN) + (size_t)d * SN;
    ulonglong2* oP = (ulonglong2*)&g_P[basei];
    ulonglong2* oS = (ulonglong2*)&g_S[basei];
    #pragma unroll
    for (int q = 0; q < 4; q++) {
        ulonglong2 vp, vs;
        vp.x = P2[2 * q]; vp.y = P2[2 * q + 1];
        vs.x = h2[2 * q]; vs.y = h2[2 * q + 1];
        oP[q] = vp; oS[q] = vs;
    }
}

// ---------------- kernel 5: scan over chunk summaries ----------------
__global__ __launch_bounds__(256) void k_phase3() {
    int s = blockIdx.x * 256 + threadIdx.x;  // D*SN threads
    float H = 0.f;
    #pragma unroll 4
    for (int c = 0; c < NC; c++) {
        size_t idx = (size_t)c * (D * SN) + s;
        g_hin[idx] = H;
        H = fmaf(g_P[idx], H, g_S[idx]);
    }
}

// ---------------- kernel 6: recompute with true init, emit y (f32x2) ----------------
__global__ __launch_bounds__(128) void k_phase4(const float* __restrict__ Dskip,
                                                float* __restrict__ y) {
    int gid = blockIdx.x * 128 + threadIdx.x;
    int c = gid >> 10;
    int d = gid & (D - 1);
    const u64 ONE2 = pack2(1.f, 1.f), TWO2 = pack2(2.f, 2.f), NONE2 = pack2(-1.f, -1.f);
    u64 cA2[8], h2[8];
    const ulonglong2* ca = (const ulonglong2*)&g_cA[d * SN];
    #pragma unroll
    for (int q = 0; q < 4; q++) {
        ulonglong2 v = ca[q];
        cA2[2 * q] = v.x; cA2[2 * q + 1] = v.y;
    }
    size_t basei = (size_t)c * (D * SN) + (size_t)d * SN;
    const ulonglong2* hi = (const ulonglong2*)&g_hin[basei];
    #pragma unroll
    for (int q = 0; q < 4; q++) {
        ulonglong2 v = hi[q];
        h2[2 * q] = v.x; h2[2 * q + 1] = v.y;
    }
    float dsk = Dskip[d];

    int t0 = c * CT;
    for (int tt = 0; tt < CT; tt++) {
        int t = t0 + tt;
        float dlv = g_delta[(size_t)t * D + d];
        float sdx = g_sdx[(size_t)t * D + d];
        float xnv = g_xn[(size_t)t * D + d];
        u64 dlv2 = pack2(dlv, dlv), sdx2 = pack2(sdx, sdx);
        const ulonglong2* bc = (const ulonglong2*)&g_bpc[(size_t)t * 2 * SN];
        u64 bp2[8], cc2[8];
        #pragma unroll
        for (int q = 0; q < 4; q++) {
            ulonglong2 vb = bc[q], vc = bc[q + 4];
            bp2[2 * q] = vb.x; bp2[2 * q + 1] = vb.y;
            cc2[2 * q] = vc.x; cc2[2 * q + 1] = vc.y;
        }
        u64 acca = 0ull, accb = 0ull;
        #pragma unroll
        for (int p = 0; p < 8; p++) {
            u64 den2 = fma2(cA2[p], dlv2, ONE2);
            float2 dd = unpack2(den2);
            u64 dinv2 = pack2(frcp(dd.x), frcp(dd.y));
            u64 ab2 = fma2(dinv2, TWO2, NONE2);
            u64 bx2 = mul2(mul2(bp2[p], dinv2), sdx2);
            h2[p] = fma2(ab2, h2[p], bx2);
            if (p & 1) accb = fma2(cc2[p], h2[p], accb);
            else       acca = fma2(cc2[p], h2[p], acca);
        }
        float2 s = unpack2(add2(acca, accb));
        y[(size_t)t * D + d] = fmaf(dsk, xnv, s.x + s.y);
    }
}

// ---------------- launch ----------------
extern "C" void kernel_launch(void* const* d_in, const int* in_sizes, int n_in,
                              void* d_out, int out_size) {
    const float* x       = (const float*)d_in[0];
    const float* A_log   = (const float*)d_in[1];
    const float* W_delta = (const float*)d_in[2];
    const float* b_delta = (const float*)d_in[3];
    const float* W_B     = (const float*)d_in[4];
    const float* W_C     = (const float*)d_in[5];
    const float* D_skip  = (const float*)d_in[6];
    const float* norm_w  = (const float*)d_in[7];
    float* y = (float*)d_out;

    cudaFuncSetAttribute(k_gemm_mma, cudaFuncAttributeMaxDynamicSharedMemorySize,
                         2 * STAGE_B);

    k_prep<<<(D * SN + 255) / 256, 256>>>(A_log);
    k_wt<<<dim3(32, 32), dim3(32, 8)>>>(W_delta);
    k_wbc<<<128 * D / 256, 256>>>(W_B, W_C);
    k_rms<<<L, 256>>>(x, norm_w);
    k_gemm_mma<<<dim3(9, 32), 256, 2 * STAGE_B>>>(b_delta);
    k_phase2<<<NC * D / 128, 128>>>();
    k_phase3<<<D * SN / 256, 256>>>();
    k_phase4<<<NC * D / 128, 128>>>(D_skip, y);
}

// round 10
// speedup vs baseline: 3.3411x; 1.0751x over previous
#include <cuda_runtime.h>
#include <cuda_fp16.h>
#include <math.h>
#include <stdint.h>

// Problem shape (fixed by dataset)
#define L   4096
#define D   1024
#define SN  16
#define NC  64      // number of chunks
#define CT  64      // chunk length; NC*CT == L

typedef unsigned long long u64;

// ---------------- scratch (static device globals; no allocation) ----------------
__device__ float g_xn[L * D];                  // normalized input (fp32)
__device__ __half g_xh[L * D];                 // fp16 hi of xn
__device__ __half g_xl[L * D];                 // fp16 lo of xn (bc tile only)
__device__ __half g_wth[D * D];                // W_delta^T fp16 [n][k]
__device__ __half g_wbch[128 * D];             // [WB|WC|0]^T hi [n][k], n<32 real
__device__ __half g_wbcl[128 * D];             // [WB|WC|0]^T lo
__device__ float g_delta[L * D];               // selective delta
__device__ float g_sdx[L * D];                 // sqrt(delta) * xn
__device__ float g_bpc[L * 2 * SN];            // per-t: Bp[0..15], C[16..31]
__device__ float g_cA[D * SN];                 // +0.5*exp(A_log)   (positive!)
__device__ float g_P[NC * D * SN];             // per-chunk product of A_bar
__device__ float g_S[NC * D * SN];             // per-chunk end-state from h0=0
__device__ float g_hin[NC * D * SN];           // per-chunk initial state

// ---------------- helpers ----------------
__device__ __forceinline__ float frcp(float x) {
    float r;
    asm("rcp.approx.f32 %0, %1;" : "=f"(r) : "f"(x));
    return r;
}
__device__ __forceinline__ uint32_t smem_u32(const void* p) {
    uint32_t a;
    asm("{ .reg .u64 t; cvta.to.shared.u64 t, %1; cvt.u32.u64 %0, t; }" : "=r"(a) : "l"(p));
    return a;
}
__device__ __forceinline__ void ldsm4(uint32_t& r0, uint32_t& r1, uint32_t& r2, uint32_t& r3,
                                      uint32_t addr) {
    asm volatile("ldmatrix.sync.aligned.m8n8.x4.shared.b16 {%0,%1,%2,%3}, [%4];"
                 : "=r"(r0), "=r"(r1), "=r"(r2), "=r"(r3) : "r"(addr));
}
__device__ __forceinline__ void mma16816(float* d, const uint32_t* a, uint32_t b0, uint32_t b1) {
    asm volatile(
        "mma.sync.aligned.m16n8k16.row.col.f32.f16.f16.f32 "
        "{%0,%1,%2,%3}, {%4,%5,%6,%7}, {%8,%9}, {%0,%1,%2,%3};"
        : "+f"(d[0]), "+f"(d[1]), "+f"(d[2]), "+f"(d[3])
        : "r"(a[0]), "r"(a[1]), "r"(a[2]), "r"(a[3]), "r"(b0), "r"(b1));
}
__device__ __forceinline__ void cp16(uint32_t dst, const void* src) {
    asm volatile("cp.async.cg.shared.global [%0], [%1], 16;" :: "r"(dst), "l"(src) : "memory");
}
__device__ __forceinline__ u64 pack2(float lo, float hi) {
    u64 r;
    asm("mov.b64 %0, {%1,%2};" : "=l"(r) : "f"(lo), "f"(hi));
    return r;
}
__device__ __forceinline__ float2 unpack2(u64 v) {
    float lo, hi;
    asm("mov.b64 {%0,%1}, %2;" : "=f"(lo), "=f"(hi) : "l"(v));
    return make_float2(lo, hi);
}
__device__ __forceinline__ u64 fma2(u64 a, u64 b, u64 c) {
    u64 d;
    asm("fma.rn.f32x2 %0, %1, %2, %3;" : "=l"(d) : "l"(a), "l"(b), "l"(c));
    return d;
}
__device__ __forceinline__ u64 mul2(u64 a, u64 b) {
    u64 d;
    asm("mul.rn.f32x2 %0, %1, %2;" : "=l"(d) : "l"(a), "l"(b));
    return d;
}
__device__ __forceinline__ u64 add2(u64 a, u64 b) {
    u64 d;
    asm("add.rn.f32x2 %0, %1, %2;" : "=l"(d) : "l"(a), "l"(b));
    return d;
}

// ---------------- kernel 0b: transpose W_delta -> fp16 ----------------
__global__ __launch_bounds__(256) void k_wt(const float* __restrict__ W) {
    __shared__ float tile[32][33];
    int bx = blockIdx.x, by = blockIdx.y;
    int tx = threadIdx.x, ty = threadIdx.y;   // 32 x 8
    #pragma unroll
    for (int i = 0; i < 32; i += 8)
        tile[ty + i][tx] = W[(size_t)(by * 32 + ty + i) * D + bx * 32 + tx];
    __syncthreads();
    #pragma unroll
    for (int i = 0; i < 32; i += 8) {
        int n = bx * 32 + ty + i;
        int k = by * 32 + tx;
        g_wth[(size_t)n * D + k] = __float2half(tile[tx][ty + i]);  // = W[k][n]
    }
}

// ---------------- kernel 0c: pack [WB|WC|0]^T fp16 hi/lo, + cA ----------------
__global__ __launch_bounds__(256) void k_wbc(const float* __restrict__ WB,
                                             const float* __restrict__ WC,
                                             const float* __restrict__ A_log) {
    int idx = blockIdx.x * 256 + threadIdx.x;   // 128*1024
    if (idx < D * SN) g_cA[idx] = 0.5f * expf(A_log[idx]);
    int n = idx >> 10, k = idx & 1023;
    float v = 0.f;
    if (n < SN) v = WB[(size_t)k * SN + n];
    else if (n < 2 * SN) v = WC[(size_t)k * SN + n - SN];
    __half h = __float2half(v);
    __half l = __float2half(v - __half2float(h));
    g_wbch[idx] = h;
    g_wbcl[idx] = l;
}

// ---------------- kernel 1: RMSNorm (+ fp16 hi/lo split of xn) ----------------
__global__ __launch_bounds__(256) void k_rms(const float* __restrict__ x,
                                             const float* __restrict__ w) {
    int row = blockIdx.x;
    int tid = threadIdx.x;
    const float4 xv = *(const float4*)(x + (size_t)row * D + tid * 4);
    float s = xv.x * xv.x + xv.y * xv.y + xv.z * xv.z + xv.w * xv.w;
    #pragma unroll
    for (int o = 16; o > 0; o >>= 1) s += __shfl_xor_sync(0xFFFFFFFFu, s, o);
    __shared__ float red[8];
    int warp = tid >> 5, lane = tid & 31;
    if (lane == 0) red[warp] = s;
    __syncthreads();
    float tot = 0.f;
    #pragma unroll
    for (int i = 0; i < 8; i++) tot += red[i];
    float inv = 1.0f / sqrtf(tot * (1.0f / (float)D) + 1e-6f);
    const float4 wv = *(const float4*)(w + tid * 4);
    float4 o;
    o.x = wv.x * xv.x * inv;
    o.y = wv.y * xv.y * inv;
    o.z = wv.z * xv.z * inv;
    o.w = wv.w * xv.w * inv;
    size_t base = (size_t)row * D + tid * 4;
    *(float4*)(&g_xn[base]) = o;
    float vv[4] = {o.x, o.y, o.z, o.w};
    __half hh[4], ll[4];
    #pragma unroll
    for (int i = 0; i < 4; i++) {
        hh[i] = __float2half(vv[i]);
        ll[i] = __float2half(vv[i] - __half2float(hh[i]));
    }
    ((__half2*)(&g_xh[base]))[0] = __halves2half2(hh[0], hh[1]);
    ((__half2*)(&g_xh[base]))[1] = __halves2half2(hh[2], hh[3]);
    ((__half2*)(&g_xl[base]))[0] = __halves2half2(ll[0], ll[1]);
    ((__half2*)(&g_xl[base]))[1] = __halves2half2(ll[2], ll[3]);
}

// ---------------- kernel 3: fused GEMM (delta + Bp/C) via mma.sync fp16 ----------------
// grid (9, 32): bn<8 -> delta path: BK=64, XOR-swizzled 128B rows, 16 iters.
//               bn==8 -> bc path: BK=32, KST=40 layout, 32 iters (proven R8 code).
// CTA tile 128x128, 8 warps each 32(m) x 64(n). cp.async 2-stage pipeline.
#define KST 40                         // bc path smem row stride in fp16 (80B)
#define TILE_B (128 * KST * 2)         // 10240 B per bc tile
#define STAGE_B (4 * TILE_B)           // 40960 B per bc stage
#define TILE2  16384                   // delta tile: 128 rows x 128B
#define STAGE2 (2 * TILE2)             // 32768 B per delta stage
#define SMEM_TOT (2 * STAGE_B)         // 81920 B (covers both layouts)
__global__ __launch_bounds__(256, 2) void k_gemm_mma(const float* __restrict__ bd) {
    extern __shared__ __align__(16) char smem[];
    const uint32_t su = smem_u32(smem);

    int tid = threadIdx.x, wid = tid >> 5, lane = tid & 31;
    int bm = blockIdx.y, bn = blockIdx.x;
    const int m0 = bm * 128, n0 = bn * 128;
    int wm = wid & 3, wn = wid >> 2;

    float acc[2][8][4];
    #pragma unroll
    for (int a = 0; a < 2; a++)
        #pragma unroll
        for (int b = 0; b < 8; b++)
            #pragma unroll
            for (int c = 0; c < 4; c++) acc[a][b][c] = 0.f;

    if (bn < 8) {
        // ================= delta path: BK=64, swizzled =================
        const __half* pA = g_xh + (size_t)m0 * D;
        const __half* pB = g_wth + (size_t)n0 * D;
        // loader mapping: id in [0,2048): tile=id>>10, row=(id&1023)>>3, kc=id&7
        int lrow = (tid & 127) >> 3 << 0;   // placeholder; computed in lambda
        (void)lrow;
        auto issue = [&](int k0, int stage) {
            uint32_t sb = su + (uint32_t)(stage * STAGE2);
            #pragma unroll
            for (int j = 0; j < 8; j++) {
                int id = tid + j * 256;
                const int tile = j >> 2;               // 0..1 (compile-time per j)
                int sub = id & 1023;
                int row = sub >> 3, kc = sub & 7;
                const __half* src = (tile == 0 ? pA : pB) + (size_t)row * D + k0 + kc * 8;
                uint32_t dst = sb + (uint32_t)(tile * TILE2 + row * 128 +
                                               ((kc ^ (row & 7)) << 4));
                cp16(dst, src);
            }
            asm volatile("cp.async.commit_group;" ::: "memory");
        };

        // per-lane ldmatrix bases (swizzle XOR term added per kk)
        int arow = wm * 32 + (lane & 15);
        int brow = wn * 64 + (lane & 7) + ((lane >> 4) << 3);
        uint32_t abase = (uint32_t)(arow * 128);
        uint32_t bbase = (uint32_t)(TILE2 + brow * 128);
        uint32_t rl = (uint32_t)(lane & 7);            // = row&7 for both A and B
        uint32_t ahalf = (uint32_t)(lane >> 4);
        uint32_t bhalf = (uint32_t)((lane >> 3) & 1);

        issue(0, 0);
        for (int i = 0; i < 16; i++) {
            if (i > 0) __syncthreads();
            if (i + 1 < 16) issue((i + 1) * 64, (i + 1) & 1);
            if (i == 15) asm volatile("cp.async.wait_group 0;" ::: "memory");
            else         asm volatile("cp.async.wait_group 1;" ::: "memory");
            __syncthreads();

            uint32_t sb = su + (uint32_t)((i & 1) * STAGE2);
            #pragma unroll
            for (int kk = 0; kk < 4; kk++) {
                uint32_t xa = (((uint32_t)(2 * kk) + ahalf) ^ rl) << 4;
                uint32_t xb = (((uint32_t)(2 * kk) + bhalf) ^ rl) << 4;
                uint32_t ah0[4], ah1[4];
                ldsm4(ah0[0], ah0[1], ah0[2], ah0[3], sb + abase + xa);
                ldsm4(ah1[0], ah1[1], ah1[2], ah1[3], sb + abase + 2048 + xa);
                #pragma unroll
                for (int nb = 0; nb < 4; nb++) {
                    uint32_t bh[4];
                    ldsm4(bh[0], bh[1], bh[2], bh[3],
                          sb + bbase + (uint32_t)(nb * 2048) + xb);
                    mma16816(acc[0][2 * nb],     ah0, bh[0], bh[1]);
                    mma16816(acc[1][2 * nb],     ah1, bh[0], bh[1]);
                    mma16816(acc[0][2 * nb + 1], ah0, bh[2], bh[3]);
                    mma16816(acc[1][2 * nb + 1], ah1, bh[2], bh[3]);
                }
            }
        }

        // epilogue: z -> delta -> (delta, sqrt(delta)*xn)
        const float CTR = 5.00005f, HLF = 4.99995f, INVH = 1.0f / 4.99995f;
        #pragma unroll
        for (int ma = 0; ma < 2; ma++) {
            int row0 = m0 + wm * 32 + ma * 16 + (lane >> 2);
            #pragma unroll
            for (int na = 0; na < 8; na++) {
                int col = n0 + wn * 64 + na * 8 + 2 * (lane & 3);
                float2 bdv = *(const float2*)(bd + col);
                #pragma unroll
                for (int hrow = 0; hrow < 2; hrow++) {
                    int m = row0 + hrow * 8;
                    float z0 = acc[ma][na][2 * hrow]     + bdv.x;
                    float z1 = acc[ma][na][2 * hrow + 1] + bdv.y;
                    float2 xv = *(const float2*)(&g_xn[(size_t)m * D + col]);
                    float sp0 = fmaxf(z0, 0.0f) + log1pf(expf(-fabsf(z0)));
                    float sp1 = fmaxf(z1, 0.0f) + log1pf(expf(-fabsf(z1)));
                    float dl0 = CTR + HLF * tanhf((sp0 - CTR) * INVH);
                    float dl1 = CTR + HLF * tanhf((sp1 - CTR) * INVH);
                    float sx0 = sqrtf(dl0) * xv.x;
                    float sx1 = sqrtf(dl1) * xv.y;
                    *(float2*)(&g_delta[(size_t)m * D + col]) = make_float2(dl0, dl1);
                    *(float2*)(&g_sdx[(size_t)m * D + col])   = make_float2(sx0, sx1);
                }
            }
        }
    } else {
        // ================= bc path: BK=32, KST=40 (R8 verbatim) =================
        const __half* pA0 = g_xh + (size_t)m0 * D;
        const __half* pA1 = g_xl + (size_t)m0 * D;
        const __half* pB0 = g_wbch;
        const __half* pB1 = g_wbcl;

        uint32_t aoff = (uint32_t)((wm * 32 + (lane & 15)) * (KST * 2) + ((lane >> 4) << 4));
        uint32_t boff = (uint32_t)((wn * 64 + (lane & 7) + ((lane >> 4) << 3)) * (KST * 2) +
                                   (((lane >> 3) & 1) << 4));

        auto issue = [&](int k0, int stage) {
            uint32_t sb = su + (uint32_t)(stage * STAGE_B);
            #pragma unroll
            for (int j = 0; j < 8; j++) {
                const int tile = j >> 1;
                int sub = tid + (j & 1) * 256;
                int row = sub >> 2, seg = sub & 3;
                const __half* src;
                if (tile == 0)      src = pA0 + (size_t)row * D + k0 + seg * 8;
                else if (tile == 1) src = pA1 + (size_t)row * D + k0 + seg * 8;
                else if (tile == 2) src = pB0 + (size_t)row * D + k0 + seg * 8;
                else                src = pB1 + (size_t)row * D + k0 + seg * 8;
                cp16(sb + (uint32_t)(tile * TILE_B + row * (KST * 2) + seg * 16), src);
            }
            asm volatile("cp.async.commit_group;" ::: "memory");
        };

        issue(0, 0);
        for (int i = 0; i < 32; i++) {
            if (i > 0) __syncthreads();
            if (i + 1 < 32) issue((i + 1) * 32, (i + 1) & 1);
            if (i == 31) asm volatile("cp.async.wait_group 0;" ::: "memory");
            else         asm volatile("cp.async.wait_group 1;" ::: "memory");
            __syncthreads();

            uint32_t sb = su + (uint32_t)((i & 1) * STAGE_B);
            uint32_t uAh = sb, uAl = sb + TILE_B, uBh = sb + 2 * TILE_B, uBl = sb + 3 * TILE_B;
            #pragma unroll
            for (int kk = 0; kk < 2; kk++) {
                uint32_t kb = (uint32_t)(kk * 32);
                uint32_t ah0[4], ah1[4];
                ldsm4(ah0[0], ah0[1], ah0[2], ah0[3], uAh + aoff + kb);
                ldsm4(ah1[0], ah1[1], ah1[2], ah1[3], uAh + aoff + kb + 16 * KST * 2);
                #pragma unroll
                for (int nb = 0; nb < 2; nb++) {      // bc: only cols 0..31
                    if (wn == 1) continue;
                    uint32_t bh[4];
                    uint32_t bo = boff + kb + (uint32_t)(nb * 16 * KST * 2);
                    ldsm4(bh[0], bh[1], bh[2], bh[3], uBh + bo);
                    mma16816(acc[0][2 * nb],     ah0, bh[0], bh[1]);
                    mma16816(acc[1][2 * nb],     ah1, bh[0], bh[1]);
                    mma16816(acc[0][2 * nb + 1], ah0, bh[2], bh[3]);
                    mma16816(acc[1][2 * nb + 1], ah1, bh[2], bh[3]);
                    uint32_t al0[4], al1[4], bl[4];
                    ldsm4(al0[0], al0[1], al0[2], al0[3], uAl + aoff + kb);
                    ldsm4(al1[0], al1[1], al1[2], al1[3], uAl + aoff + kb + 16 * KST * 2);
                    ldsm4(bl[0], bl[1], bl[2], bl[3], uBl + bo);
                    mma16816(acc[0][2 * nb],     al0, bh[0], bh[1]);
                    mma16816(acc[1][2 * nb],     al1, bh[0], bh[1]);
                    mma16816(acc[0][2 * nb + 1], al0, bh[2], bh[3]);
                    mma16816(acc[1][2 * nb + 1], al1, bh[2], bh[3]);
                    mma16816(acc[0][2 * nb],     ah0, bl[0], bl[1]);
                    mma16816(acc[1][2 * nb],     ah1, bl[0], bl[1]);
                    mma16816(acc[0][2 * nb + 1], ah0, bl[2], bl[3]);
                    mma16816(acc[1][2 * nb + 1], ah1, bl[2], bl[3]);
                }
            }
        }

        if (wn == 0) {
            // bc epilogue: raw z -> g_bpc[t][0..31]
            #pragma unroll
            for (int ma = 0; ma < 2; ma++) {
                int row0 = m0 + wm * 32 + ma * 16 + (lane >> 2);
                #pragma unroll
                for (int na = 0; na < 4; na++) {
                    int col = na * 8 + 2 * (lane & 3);
                    #pragma unroll
                    for (int hrow = 0; hrow < 2; hrow++) {
                        int m = row0 + hrow * 8;
                        *(float2*)(&g_bpc[(size_t)m * 2 * SN + col]) =
                            make_float2(acc[ma][na][2 * hrow], acc[ma][na][2 * hrow + 1]);
                    }
                }
            }
        }
    }
}

// ---------------- kernel 4: chunk-local scan, f32x2 packed ----------------
__global__ __launch_bounds__(128) void k_phase2() {
    int gid = blockIdx.x * 128 + threadIdx.x;   // NC*D threads
    int c = gid >> 10;
    int d = gid & (D - 1);
    const u64 ONE2 = pack2(1.f, 1.f), TWO2 = pack2(2.f, 2.f), NONE2 = pack2(-1.f, -1.f);
    u64 cA2[8], h2[8], P2[8];
    const ulonglong2* ca = (const ulonglong2*)&g_cA[d * SN];
    #pragma unroll
    for (int q = 0; q < 4; q++) {
        ulonglong2 v = ca[q];
        cA2[2 * q] = v.x; cA2[2 * q + 1] = v.y;
    }
    #pragma unroll
    for (int p = 0; p < 8; p++) { h2[p] = 0ull; P2[p] = ONE2; }

    int t0 = c * CT;
    for (int tt = 0; tt < CT; tt++) {
        int t = t0 + tt;
        float dlv = g_delta[(size_t)t * D + d];
        float sdx = g_sdx[(size_t)t * D + d];
        u64 dlv2 = pack2(dlv, dlv), sdx2 = pack2(sdx, sdx);
        const ulonglong2* bp = (const ulonglong2*)&g_bpc[(size_t)t * 2 * SN];
        u64 bp2[8];
        #pragma unroll
        for (int q = 0; q < 4; q++) {
            ulonglong2 v = bp[q];
            bp2[2 * q] = v.x; bp2[2 * q + 1] = v.y;
        }
        #pragma unroll
        for (int p = 0; p < 8; p++) {
            u64 den2 = fma2(cA2[p], dlv2, ONE2);       // 1 + 0.5*delta*|A| > 1
            float2 dd = unpack2(den2);
            u64 dinv2 = pack2(frcp(dd.x), frcp(dd.y));
            u64 ab2 = fma2(dinv2, TWO2, NONE2);        // (1+hf)/(1-hf) = 2*dinv - 1
            u64 bx2 = mul2(mul2(bp2[p], dinv2), sdx2);
            h2[p] = fma2(ab2, h2[p], bx2);
            P2[p] = mul2(P2[p], ab2);
        }
    }
    size_t basei = (size_t)c * (D * SN) + (size_t)d * SN;
    ulonglong2* oP = (ulonglong2*)&g_P[basei];
    ulonglong2* oS = (ulonglong2*)&g_S[basei];
    #pragma unroll
    for (int q = 0; q < 4; q++) {
        ulonglong2 vp, vs;
        vp.x = P2[2 * q]; vp.y = P2[2 * q + 1];
        vs.x = h2[2 * q]; vs.y = h2[2 * q + 1];
        oP[q] = vp; oS[q] = vs;
    }
}

// ---------------- kernel 5: scan over chunk summaries ----------------
__global__ __launch_bounds__(256) void k_phase3() {
    int s = blockIdx.x * 256 + threadIdx.x;  // D*SN threads
    float H = 0.f;
    #pragma unroll 4
    for (int c = 0; c < NC; c++) {
        size_t idx = (size_t)c * (D * SN) + s;
        g_hin[idx] = H;
        H = fmaf(g_P[idx], H, g_S[idx]);
    }
}

// ---------------- kernel 6: recompute with true init, emit y (f32x2) ----------------
__global__ __launch_bounds__(128) void k_phase4(const float* __restrict__ Dskip,
                                                float* __restrict__ y) {
    int gid = blockIdx.x * 128 + threadIdx.x;
    int c = gid >> 10;
    int d = gid & (D - 1);
    const u64 ONE2 = pack2(1.f, 1.f), TWO2 = pack2(2.f, 2.f), NONE2 = pack2(-1.f, -1.f);
    u64 cA2[8], h2[8];
    const ulonglong2* ca = (const ulonglong2*)&g_cA[d * SN];
    #pragma unroll
    for (int q = 0; q < 4; q++) {
        ulonglong2 v = ca[q];
        cA2[2 * q] = v.x; cA2[2 * q + 1] = v.y;
    }
    size_t basei = (size_t)c * (D * SN) + (size_t)d * SN;
    const ulonglong2* hi = (const ulonglong2*)&g_hin[basei];
    #pragma unroll
    for (int q = 0; q < 4; q++) {
        ulonglong2 v = hi[q];
        h2[2 * q] = v.x; h2[2 * q + 1] = v.y;
    }
    float dsk = Dskip[d];

    int t0 = c * CT;
    for (int tt = 0; tt < CT; tt++) {
        int t = t0 + tt;
        float dlv = g_delta[(size_t)t * D + d];
        float sdx = g_sdx[(size_t)t * D + d];
        float xnv = g_xn[(size_t)t * D + d];
        u64 dlv2 = pack2(dlv, dlv), sdx2 = pack2(sdx, sdx);
        const ulonglong2* bc = (const ulonglong2*)&g_bpc[(size_t)t * 2 * SN];
        u64 bp2[8], cc2[8];
        #pragma unroll
        for (int q = 0; q < 4; q++) {
            ulonglong2 vb = bc[q], vc = bc[q + 4];
            bp2[2 * q] = vb.x; bp2[2 * q + 1] = vb.y;
            cc2[2 * q] = vc.x; cc2[2 * q + 1] = vc.y;
        }
        u64 acca = 0ull, accb = 0ull;
        #pragma unroll
        for (int p = 0; p < 8; p++) {
            u64 den2 = fma2(cA2[p], dlv2, ONE2);
            float2 dd = unpack2(den2);
            u64 dinv2 = pack2(frcp(dd.x), frcp(dd.y));
            u64 ab2 = fma2(dinv2, TWO2, NONE2);
            u64 bx2 = mul2(mul2(bp2[p], dinv2), sdx2);
            h2[p] = fma2(ab2, h2[p], bx2);
            if (p & 1) accb = fma2(cc2[p], h2[p], accb);
            else       acca = fma2(cc2[p], h2[p], acca);
        }
        float2 s = unpack2(add2(acca, accb));
        y[(size_t)t * D + d] = fmaf(dsk, xnv, s.x + s.y);
    }
}

// ---------------- launch ----------------
extern "C" void kernel_launch(void* const* d_in, const int* in_sizes, int n_in,
                              void* d_out, int out_size) {
    const float* x       = (const float*)d_in[0];
    const float* A_log   = (const float*)d_in[1];
    const float* W_delta = (const float*)d_in[2];
    const float* b_delta = (const float*)d_in[3];
    const float* W_B     = (const float*)d_in[4];
    const float* W_C     = (const float*)d_in[5];
    const float* D_skip  = (const float*)d_in[6];
    const float* norm_w  = (const float*)d_in[7];
    float* y = (float*)d_out;

    cudaFuncSetAttribute(k_gemm_mma, cudaFuncAttributeMaxDynamicSharedMemorySize,
                         SMEM_TOT);

    k_wt<<<dim3(32, 32), dim3(32, 8)>>>(W_delta);
    k_wbc<<<128 * D / 256, 256>>>(W_B, W_C, A_log);
    k_rms<<<L, 256>>>(x, norm_w);
    k_gemm_mma<<<dim3(9, 32), 256, SMEM_TOT>>>(b_delta);
    k_phase2<<<NC * D / 128, 128>>>();
    k_phase3<<<D * SN / 256, 256>>>();
    k_phase4<<<NC * D / 128, 128>>>(D_skip, y);
}